// round 7
// baseline (speedup 1.0000x reference)
#include <cuda_runtime.h>
#include <cuda_bf16.h>
#include <cstdint>

#define BATCH  2
#define SEQ    2048
#define DMODEL 1024
#define NHEAD  16
#define HDIM   64
#define MROWS  (BATCH * SEQ)       // 4096

// ---------------------------------------------------------------------------
// Scratch (allocation-free rule: __device__ globals)
// ---------------------------------------------------------------------------
__device__ __nv_bfloat16 g_xh[MROWS * DMODEL];      // x split hi/lo
__device__ __nv_bfloat16 g_xl[MROWS * DMODEL];
__device__ __nv_bfloat16 g_wh[4][DMODEL * DMODEL];  // wq,wk,wv,wo hi
__device__ __nv_bfloat16 g_wl[4][DMODEL * DMODEL];  // wq,wk,wv,wo lo
// q/k split, [b*NHEAD+h][s][hd]; q pre-scaled by 0.125
__device__ __nv_bfloat16 g_qh[MROWS * DMODEL];
__device__ __nv_bfloat16 g_ql[MROWS * DMODEL];
__device__ __nv_bfloat16 g_kh[MROWS * DMODEL];
__device__ __nv_bfloat16 g_kl[MROWS * DMODEL];
// v split TRANSPOSED: [b*NHEAD+h][hd][s]
__device__ __nv_bfloat16 g_vh[MROWS * DMODEL];
__device__ __nv_bfloat16 g_vl[MROWS * DMODEL];
// ctx split, [b*s][d]
__device__ __nv_bfloat16 g_ch[MROWS * DMODEL];
__device__ __nv_bfloat16 g_cl[MROWS * DMODEL];

// ---------------------------------------------------------------------------
// Warp-MMA + cp.async helpers (base compute_103 PTX)
// ---------------------------------------------------------------------------
__device__ __forceinline__ uint32_t smem_u32(const void* p) {
    uint32_t a;
    asm("{ .reg .u64 t; cvta.to.shared.u64 t, %1; cvt.u32.u64 %0, t; }"
        : "=r"(a) : "l"(p));
    return a;
}

__device__ __forceinline__ void ldmatrix_x4(uint32_t* r, uint32_t addr) {
    asm volatile("ldmatrix.sync.aligned.m8n8.x4.shared.b16 {%0,%1,%2,%3}, [%4];"
                 : "=r"(r[0]), "=r"(r[1]), "=r"(r[2]), "=r"(r[3]) : "r"(addr));
}

__device__ __forceinline__ void mma_bf16(float* c, const uint32_t* a, const uint32_t* b) {
    asm volatile(
        "mma.sync.aligned.m16n8k16.row.col.f32.bf16.bf16.f32 "
        "{%0,%1,%2,%3}, {%4,%5,%6,%7}, {%8,%9}, {%0,%1,%2,%3};"
        : "+f"(c[0]), "+f"(c[1]), "+f"(c[2]), "+f"(c[3])
        : "r"(a[0]), "r"(a[1]), "r"(a[2]), "r"(a[3]), "r"(b[0]), "r"(b[1]));
}

__device__ __forceinline__ void cp_async16(uint32_t dst, const void* src) {
    asm volatile("cp.async.cg.shared.global [%0], [%1], 16;" :: "r"(dst), "l"(src));
}
#define CP_COMMIT() asm volatile("cp.async.commit_group;" ::: "memory")
#define CP_WAIT0()  asm volatile("cp.async.wait_group 0;" ::: "memory")

__device__ __forceinline__ void split2(float v, __nv_bfloat16& h, __nv_bfloat16& l) {
    h = __float2bfloat16(v);
    l = __float2bfloat16(v - __bfloat162float(h));
}

// ---------------------------------------------------------------------------
// fp32 -> (bf16 hi, bf16 lo) split (x and weights only)
// ---------------------------------------------------------------------------
__global__ __launch_bounds__(256)
void split_bf16_kernel(const float* __restrict__ in,
                       __nv_bfloat16* __restrict__ hi,
                       __nv_bfloat16* __restrict__ lo, int n)
{
    int i4 = (blockIdx.x * blockDim.x + threadIdx.x) * 4;
    if (i4 >= n) return;
    float4 f = *reinterpret_cast<const float4*>(in + i4);
    float fs[4] = {f.x, f.y, f.z, f.w};
    __nv_bfloat162 hv[2], lv[2];
    #pragma unroll
    for (int j = 0; j < 2; j++) {
        __nv_bfloat16 h0, h1, l0, l1;
        split2(fs[2 * j], h0, l0);
        split2(fs[2 * j + 1], h1, l1);
        hv[j].x = h0; hv[j].y = h1;
        lv[j].x = l0; lv[j].y = l1;
    }
    *reinterpret_cast<__nv_bfloat162*>(hi + i4)     = hv[0];
    *reinterpret_cast<__nv_bfloat162*>(hi + i4 + 2) = hv[1];
    *reinterpret_cast<__nv_bfloat162*>(lo + i4)     = lv[0];
    *reinterpret_cast<__nv_bfloat162*>(lo + i4 + 2) = lv[1];
}

// ---------------------------------------------------------------------------
// GEMM tiling constants (shared by both GEMM kernels)
// CTA 128x128 tile, 8 warps (2x4), warp tile 64x32, K-chunk 64, 2 stages.
// ---------------------------------------------------------------------------
#define LDT       72
#define TILE_ELEM (128 * LDT)
#define TILE_B    (TILE_ELEM * 2)        // 18432 bytes
#define STAGE_B   (4 * TILE_B)           // 73728 bytes
#define GEMM_SMEM (2 * STAGE_B)          // 147456 bytes

// Mainloop macro-free shared body via inline function is awkward with lambdas
// capturing different pointers; both kernels carry their own copy.

// ---------------------------------------------------------------------------
// Merged QKV GEMM: grid (24, 32); which = blockIdx.x>>3 selects wq/wk/wv.
// which 0/1 -> MODE1 write (q or k, [bh][s][hd], q scaled 0.125)
// which 2   -> MODE2 write (v^T, [bh][hd][s])
// ---------------------------------------------------------------------------
__global__ __launch_bounds__(256)
void mma_gemm_qkv(const __nv_bfloat16* __restrict__ xh,
                  const __nv_bfloat16* __restrict__ xl,
                  const __nv_bfloat16* __restrict__ wh,
                  const __nv_bfloat16* __restrict__ wl,
                  const float* __restrict__ bq,
                  const float* __restrict__ bk,
                  const float* __restrict__ bv,
                  __nv_bfloat16* __restrict__ qh,
                  __nv_bfloat16* __restrict__ ql,
                  __nv_bfloat16* __restrict__ kh,
                  __nv_bfloat16* __restrict__ kl,
                  __nv_bfloat16* __restrict__ vh,
                  __nv_bfloat16* __restrict__ vl)
{
    extern __shared__ __align__(16) char smem[];
    const uint32_t sbase = smem_u32(smem);

    const int tid  = threadIdx.x;
    const int wid  = tid >> 5;
    const int lane = tid & 31;
    const int which = blockIdx.x >> 3;
    const int nBase = (blockIdx.x & 7) * 128;
    const int mBase = blockIdx.y * 128;
    const int warp_m = (wid >> 2) * 64;
    const int warp_n = (wid & 3) * 32;

    const size_t NW = (size_t)DMODEL * DMODEL;
    const __nv_bfloat16* Bh = wh + which * NW;
    const __nv_bfloat16* Bl = wl + which * NW;
    const float* bias = (which == 0) ? bq : (which == 1) ? bk : bv;
    const float scale = (which == 0) ? 0.125f : 1.0f;
    const __nv_bfloat16* srcs[4] = {xh, xl, Bh, Bl};

    auto stage = [&](uint32_t sdst, int kc) {
        #pragma unroll
        for (int t = 0; t < 4; t++) {
            const __nv_bfloat16* src = srcs[t];
            const int rb = (t < 2) ? mBase : nBase;
            #pragma unroll
            for (int it = 0; it < 4; it++) {
                const int slot = tid + it * 256;
                const int row  = slot >> 3;
                const int c8   = slot & 7;
                cp_async16(sdst + t * TILE_B + 2 * (uint32_t)(row * LDT + c8 * 8),
                           src + (size_t)(rb + row) * DMODEL + kc + c8 * 8);
            }
        }
    };

    float acc[4][4][4];
    #pragma unroll
    for (int mi = 0; mi < 4; mi++)
        #pragma unroll
        for (int ni = 0; ni < 4; ni++)
            #pragma unroll
            for (int e = 0; e < 4; e++) acc[mi][ni][e] = 0.0f;

    const uint32_t aRow = (uint32_t)(warp_m + (lane & 15)) * LDT + (lane >> 4) * 8;
    // x4 B pattern: pair np covers n-frags 2np,2np+1
    const uint32_t bRow = (uint32_t)(warp_n + 8 * (lane >> 4) + (lane & 7)) * LDT
                          + 8 * ((lane >> 3) & 1);

    stage(sbase, 0);
    CP_COMMIT();

    int cur = 0;
    for (int kc = 0; kc < DMODEL; kc += 64) {
        CP_WAIT0();
        __syncthreads();
        if (kc + 64 < DMODEL) {
            stage(sbase + (uint32_t)((cur ^ 1) * STAGE_B), kc + 64);
            CP_COMMIT();
        }

        const uint32_t uA = sbase + (uint32_t)(cur * STAGE_B) + 2 * aRow;
        const uint32_t uB = sbase + (uint32_t)(cur * STAGE_B + 2 * TILE_B) + 2 * bRow;

        #pragma unroll
        for (int ks = 0; ks < 4; ks++) {
            const uint32_t kOff = 2 * (uint32_t)(ks * 16);
            uint32_t ah[4][4], al[4][4], bh4[2][4], bl4[2][4];
            #pragma unroll
            for (int mi = 0; mi < 4; mi++) {
                const uint32_t addr = uA + kOff + 2 * (uint32_t)(mi * 16) * LDT;
                ldmatrix_x4(ah[mi], addr);
                ldmatrix_x4(al[mi], addr + TILE_B);
            }
            #pragma unroll
            for (int np = 0; np < 2; np++) {
                const uint32_t addr = uB + kOff + 2 * (uint32_t)(np * 16) * LDT;
                ldmatrix_x4(bh4[np], addr);
                ldmatrix_x4(bl4[np], addr + TILE_B);
            }
            #pragma unroll
            for (int mi = 0; mi < 4; mi++)
                #pragma unroll
                for (int ni = 0; ni < 4; ni++) {
                    const uint32_t* bh = &bh4[ni >> 1][2 * (ni & 1)];
                    const uint32_t* bl = &bl4[ni >> 1][2 * (ni & 1)];
                    mma_bf16(acc[mi][ni], ah[mi], bh);
                    mma_bf16(acc[mi][ni], al[mi], bh);
                    mma_bf16(acc[mi][ni], ah[mi], bl);
                }
        }
        cur ^= 1;
    }

    __nv_bfloat16* outH = (which == 0) ? qh : (which == 1) ? kh : vh;
    __nv_bfloat16* outL = (which == 0) ? ql : (which == 1) ? kl : vl;

    const int rBase = mBase + warp_m + (lane >> 2);
    const int cBase = nBase + warp_n + (lane & 3) * 2;
    #pragma unroll
    for (int mi = 0; mi < 4; mi++) {
        #pragma unroll
        for (int ni = 0; ni < 4; ni++) {
            #pragma unroll
            for (int half = 0; half < 2; half++) {
                const int m = rBase + mi * 16 + half * 8;
                const int n = cBase + ni * 8;
                const float v0 = (acc[mi][ni][half * 2]     + bias[n])     * scale;
                const float v1 = (acc[mi][ni][half * 2 + 1] + bias[n + 1]) * scale;
                const int b  = m >> 11;
                const int s  = m & 2047;
                const int h  = n >> 6;
                const int hd = n & 63;
                if (which < 2) {
                    const size_t idx = (((size_t)(b * NHEAD + h) * SEQ) + s) * HDIM + hd;
                    __nv_bfloat162 hv, lv;
                    split2(v0, hv.x, lv.x);
                    split2(v1, hv.y, lv.y);
                    *reinterpret_cast<__nv_bfloat162*>(outH + idx) = hv;
                    *reinterpret_cast<__nv_bfloat162*>(outL + idx) = lv;
                } else {
                    const size_t idx = (((size_t)(b * NHEAD + h) * HDIM) + hd) * SEQ + s;
                    __nv_bfloat16 h0, l0, h1, l1;
                    split2(v0, h0, l0);
                    split2(v1, h1, l1);
                    outH[idx]       = h0;
                    outL[idx]       = l0;
                    outH[idx + SEQ] = h1;
                    outL[idx + SEQ] = l1;
                }
            }
        }
    }
}

// ---------------------------------------------------------------------------
// Output-projection GEMM (fp32 out), same mainloop with x4 B loads.
// ---------------------------------------------------------------------------
__global__ __launch_bounds__(256)
void mma_gemm_out(const __nv_bfloat16* __restrict__ Ah,
                  const __nv_bfloat16* __restrict__ Al,
                  const __nv_bfloat16* __restrict__ Bh,
                  const __nv_bfloat16* __restrict__ Bl,
                  const float* __restrict__ bias,
                  float* __restrict__ out)
{
    extern __shared__ __align__(16) char smem[];
    const uint32_t sbase = smem_u32(smem);

    const int tid  = threadIdx.x;
    const int wid  = tid >> 5;
    const int lane = tid & 31;
    const int mBase = blockIdx.y * 128;
    const int nBase = blockIdx.x * 128;
    const int warp_m = (wid >> 2) * 64;
    const int warp_n = (wid & 3) * 32;

    const __nv_bfloat16* srcs[4] = {Ah, Al, Bh, Bl};

    auto stage = [&](uint32_t sdst, int kc) {
        #pragma unroll
        for (int t = 0; t < 4; t++) {
            const __nv_bfloat16* src = srcs[t];
            const int rb = (t < 2) ? mBase : nBase;
            #pragma unroll
            for (int it = 0; it < 4; it++) {
                const int slot = tid + it * 256;
                const int row  = slot >> 3;
                const int c8   = slot & 7;
                cp_async16(sdst + t * TILE_B + 2 * (uint32_t)(row * LDT + c8 * 8),
                           src + (size_t)(rb + row) * DMODEL + kc + c8 * 8);
            }
        }
    };

    float acc[4][4][4];
    #pragma unroll
    for (int mi = 0; mi < 4; mi++)
        #pragma unroll
        for (int ni = 0; ni < 4; ni++)
            #pragma unroll
            for (int e = 0; e < 4; e++) acc[mi][ni][e] = 0.0f;

    const uint32_t aRow = (uint32_t)(warp_m + (lane & 15)) * LDT + (lane >> 4) * 8;
    const uint32_t bRow = (uint32_t)(warp_n + 8 * (lane >> 4) + (lane & 7)) * LDT
                          + 8 * ((lane >> 3) & 1);

    stage(sbase, 0);
    CP_COMMIT();

    int cur = 0;
    for (int kc = 0; kc < DMODEL; kc += 64) {
        CP_WAIT0();
        __syncthreads();
        if (kc + 64 < DMODEL) {
            stage(sbase + (uint32_t)((cur ^ 1) * STAGE_B), kc + 64);
            CP_COMMIT();
        }

        const uint32_t uA = sbase + (uint32_t)(cur * STAGE_B) + 2 * aRow;
        const uint32_t uB = sbase + (uint32_t)(cur * STAGE_B + 2 * TILE_B) + 2 * bRow;

        #pragma unroll
        for (int ks = 0; ks < 4; ks++) {
            const uint32_t kOff = 2 * (uint32_t)(ks * 16);
            uint32_t ah[4][4], al[4][4], bh4[2][4], bl4[2][4];
            #pragma unroll
            for (int mi = 0; mi < 4; mi++) {
                const uint32_t addr = uA + kOff + 2 * (uint32_t)(mi * 16) * LDT;
                ldmatrix_x4(ah[mi], addr);
                ldmatrix_x4(al[mi], addr + TILE_B);
            }
            #pragma unroll
            for (int np = 0; np < 2; np++) {
                const uint32_t addr = uB + kOff + 2 * (uint32_t)(np * 16) * LDT;
                ldmatrix_x4(bh4[np], addr);
                ldmatrix_x4(bl4[np], addr + TILE_B);
            }
            #pragma unroll
            for (int mi = 0; mi < 4; mi++)
                #pragma unroll
                for (int ni = 0; ni < 4; ni++) {
                    const uint32_t* bh = &bh4[ni >> 1][2 * (ni & 1)];
                    const uint32_t* bl = &bl4[ni >> 1][2 * (ni & 1)];
                    mma_bf16(acc[mi][ni], ah[mi], bh);
                    mma_bf16(acc[mi][ni], al[mi], bh);
                    mma_bf16(acc[mi][ni], ah[mi], bl);
                }
        }
        cur ^= 1;
    }

    const int rBase = mBase + warp_m + (lane >> 2);
    const int cBase = nBase + warp_n + (lane & 3) * 2;
    #pragma unroll
    for (int mi = 0; mi < 4; mi++) {
        #pragma unroll
        for (int ni = 0; ni < 4; ni++) {
            #pragma unroll
            for (int half = 0; half < 2; half++) {
                const int m = rBase + mi * 16 + half * 8;
                const int n = cBase + ni * 8;
                out[(size_t)m * DMODEL + n]     = acc[mi][ni][half * 2]     + bias[n];
                out[(size_t)m * DMODEL + n + 1] = acc[mi][ni][half * 2 + 1] + bias[n + 1];
            }
        }
    }
}

// ---------------------------------------------------------------------------
// Tensor-core flash attention (causal), split-bf16, cp.async double-buffered.
// q-tile 128 rows, 256 threads (8 warps; warp owns 16 q-rows), k-tile 64.
// grid = (SEQ/128, BATCH*NHEAD). Q pre-scaled 0.125; V^T [bh][hd][s].
// Smem: stage s at s*36864 {Kh,Kl,Vh,Vl each 64x72}; P (128x72 hi/lo) at 73728.
// ---------------------------------------------------------------------------
#define ALDT   72
#define AT_B   9216                        // 64x72 bf16 tile, bytes
#define AST_B  (4 * AT_B)                  // 36864
#define P_OFF  (2 * AST_B)                 // 73728
#define PT_B   (128 * ALDT * 2)            // 18432 (128x72 tile)
#define ATTN_SMEM (P_OFF + 2 * PT_B)       // 110592

__global__ __launch_bounds__(256)
void attn_mma_kernel()
{
    extern __shared__ __align__(16) char asmem[];
    __nv_bfloat16* sM = reinterpret_cast<__nv_bfloat16*>(asmem);
    const uint32_t abase = smem_u32(asmem);

    const int tid  = threadIdx.x;
    const int w    = tid >> 5;
    const int lane = tid & 31;
    const int qi   = gridDim.x - 1 - blockIdx.x;    // long CTAs first
    const int bh   = blockIdx.y;
    const int qBase = qi * 128;
    const int nkt  = 2 * qi + 2;
    const size_t hOff = (size_t)bh * SEQ * HDIM;    // q,k: [bh][s][hd]
    const size_t vOff = (size_t)bh * HDIM * SEQ;    // v^T: [bh][hd][s]

    // K/V stage loader: 64 rows x 8 chunks x 4 arrays / 256 thr = 8 cp.async
    auto stageKV = [&](uint32_t su, int kBase) {
        #pragma unroll
        for (int it = 0; it < 2; it++) {
            const int slot = tid + it * 256;          // 0..511
            const int row = slot >> 3, c8 = slot & 7;
            const uint32_t so = 2 * (uint32_t)(row * ALDT + c8 * 8);
            const size_t gk = hOff + (size_t)(kBase + row) * HDIM + c8 * 8;
            cp_async16(su + so,            g_kh + gk);
            cp_async16(su + AT_B + so,     g_kl + gk);
            const size_t gv = vOff + (size_t)row * SEQ + kBase + c8 * 8;
            cp_async16(su + 2 * AT_B + so, g_vh + gv);
            cp_async16(su + 3 * AT_B + so, g_vl + gv);
        }
    };

    stageKV(abase, 0);
    CP_COMMIT();

    // Stage Q (128x64 hi/lo) through P buffers; pull A-frags to registers
    {
        __nv_bfloat16* sPh = sM + P_OFF / 2;
        __nv_bfloat16* sPl = sPh + PT_B / 2;
        #pragma unroll
        for (int it = 0; it < 4; it++) {
            const int slot = tid + it * 256;          // 0..1023
            const int row = slot >> 3, c8 = slot & 7;
            const size_t g = hOff + (size_t)(qBase + row) * HDIM + c8 * 8;
            *reinterpret_cast<uint4*>(sPh + row * ALDT + c8 * 8) =
                *reinterpret_cast<const uint4*>(g_qh + g);
            *reinterpret_cast<uint4*>(sPl + row * ALDT + c8 * 8) =
                *reinterpret_cast<const uint4*>(g_ql + g);
        }
    }
    __syncthreads();

    uint32_t qh[4][4], ql[4][4];
    {
        const uint32_t qa = abase + P_OFF +
            2 * ((uint32_t)(w * 16 + (lane & 15)) * ALDT + (lane >> 4) * 8);
        #pragma unroll
        for (int t = 0; t < 4; t++) {
            ldmatrix_x4(qh[t], qa + 32 * t);
            ldmatrix_x4(ql[t], qa + PT_B + 32 * t);
        }
    }

    float O[8][4];
    #pragma unroll
    for (int j = 0; j < 8; j++)
        #pragma unroll
        for (int e = 0; e < 4; e++) O[j][e] = 0.0f;
    float m0 = -1e30f, m1 = -1e30f, l0 = 0.0f, l1 = 0.0f;

    const int rl0 = w * 16 + (lane >> 2);       // local row (0..127)
    const int c0  = 2 * (lane & 3);
    const uint32_t pa = abase + P_OFF +
        2 * ((uint32_t)(w * 16 + (lane & 15)) * ALDT + (lane >> 4) * 8);

    int cur = 0;
    for (int kt = 0; kt < nkt; kt++) {
        const int kBase = kt * 64;
        CP_WAIT0();
        __syncthreads();
        if (kt + 1 < nkt) {
            stageKV(abase + (uint32_t)((cur ^ 1) * AST_B), (kt + 1) * 64);
            CP_COMMIT();
        }
        const uint32_t uK = abase + (uint32_t)(cur * AST_B);
        const uint32_t uV = uK + 2 * AT_B;
        cur ^= 1;

        const int d = kBase - qBase;            // k-col offset vs local rows
        if (d > w * 16 + 15) continue;          // warp fully masked (no CTA barriers below)

        // --- S = Q K^T (split: hh + lh + hl), x4 B loads (frag pairs) ---
        float s[8][4];
        #pragma unroll
        for (int j = 0; j < 8; j++)
            #pragma unroll
            for (int e = 0; e < 4; e++) s[j][e] = 0.0f;

        #pragma unroll
        for (int t = 0; t < 4; t++) {
            #pragma unroll
            for (int jj = 0; jj < 4; jj++) {
                const uint32_t ba = uK + 2 * ((uint32_t)(16 * jj + 8 * (lane >> 4) + (lane & 7)) * ALDT
                                              + 16 * t + 8 * ((lane >> 3) & 1));
                uint32_t kh4[4], kl4[4];
                ldmatrix_x4(kh4, ba);
                ldmatrix_x4(kl4, ba + AT_B);
                mma_bf16(s[2 * jj],     qh[t], kh4);
                mma_bf16(s[2 * jj],     ql[t], kh4);
                mma_bf16(s[2 * jj],     qh[t], kl4);
                mma_bf16(s[2 * jj + 1], qh[t], kh4 + 2);
                mma_bf16(s[2 * jj + 1], ql[t], kh4 + 2);
                mma_bf16(s[2 * jj + 1], qh[t], kl4 + 2);
            }
        }

        // --- Causal mask: col + d > row  (only possible on last two tiles) ---
        if (kt >= nkt - 2) {
            #pragma unroll
            for (int j = 0; j < 8; j++) {
                #pragma unroll
                for (int e = 0; e < 2; e++) {
                    const int col = 8 * j + c0 + e + d;
                    if (col > rl0)     s[j][e]     = -1e30f;
                    if (col > rl0 + 8) s[j][2 + e] = -1e30f;
                }
            }
        }

        // --- Online softmax ---
        float mt0 = -1e30f, mt1 = -1e30f;
        #pragma unroll
        for (int j = 0; j < 8; j++) {
            mt0 = fmaxf(mt0, fmaxf(s[j][0], s[j][1]));
            mt1 = fmaxf(mt1, fmaxf(s[j][2], s[j][3]));
        }
        mt0 = fmaxf(mt0, __shfl_xor_sync(0xffffffffu, mt0, 1));
        mt0 = fmaxf(mt0, __shfl_xor_sync(0xffffffffu, mt0, 2));
        mt1 = fmaxf(mt1, __shfl_xor_sync(0xffffffffu, mt1, 1));
        mt1 = fmaxf(mt1, __shfl_xor_sync(0xffffffffu, mt1, 2));

        const float mn0 = fmaxf(m0, mt0);
        const float mn1 = fmaxf(m1, mt1);
        const float cr0 = __expf(m0 - mn0);
        const float cr1 = __expf(m1 - mn1);
        m0 = mn0; m1 = mn1;

        float ls0 = 0.0f, ls1 = 0.0f;
        #pragma unroll
        for (int j = 0; j < 8; j++) {
            s[j][0] = __expf(s[j][0] - mn0);
            s[j][1] = __expf(s[j][1] - mn0);
            s[j][2] = __expf(s[j][2] - mn1);
            s[j][3] = __expf(s[j][3] - mn1);
            ls0 += s[j][0] + s[j][1];
            ls1 += s[j][2] + s[j][3];
        }
        ls0 += __shfl_xor_sync(0xffffffffu, ls0, 1);
        ls0 += __shfl_xor_sync(0xffffffffu, ls0, 2);
        ls1 += __shfl_xor_sync(0xffffffffu, ls1, 1);
        ls1 += __shfl_xor_sync(0xffffffffu, ls1, 2);
        l0 = l0 * cr0 + ls0;
        l1 = l1 * cr1 + ls1;
        #pragma unroll
        for (int j = 0; j < 8; j++) {
            O[j][0] *= cr0; O[j][1] *= cr0;
            O[j][2] *= cr1; O[j][3] *= cr1;
        }

        // --- Store P (hi/lo) into P buffers: same-warp rows only ---
        __nv_bfloat16* sPh = sM + P_OFF / 2;
        __nv_bfloat16* sPl = sPh + PT_B / 2;
        #pragma unroll
        for (int j = 0; j < 8; j++) {
            const int col = 8 * j + c0;
            __nv_bfloat162 hv, lv;
            split2(s[j][0], hv.x, lv.x);
            split2(s[j][1], hv.y, lv.y);
            *reinterpret_cast<__nv_bfloat162*>(sPh + rl0 * ALDT + col) = hv;
            *reinterpret_cast<__nv_bfloat162*>(sPl + rl0 * ALDT + col) = lv;
            split2(s[j][2], hv.x, lv.x);
            split2(s[j][3], hv.y, lv.y);
            *reinterpret_cast<__nv_bfloat162*>(sPh + (rl0 + 8) * ALDT + col) = hv;
            *reinterpret_cast<__nv_bfloat162*>(sPl + (rl0 + 8) * ALDT + col) = lv;
        }
        __syncwarp();

        // --- O += P V (x4 V loads, frag pairs) ---
        #pragma unroll
        for (int t = 0; t < 4; t++) {
            uint32_t ph4[4], pl4[4];
            ldmatrix_x4(ph4, pa + 32 * t);
            ldmatrix_x4(pl4, pa + PT_B + 32 * t);
            #pragma unroll
            for (int jj = 0; jj < 4; jj++) {
                const uint32_t va = uV + 2 * ((uint32_t)(16 * jj + 8 * (lane >> 4) + (lane & 7)) * ALDT
                                              + 16 * t + 8 * ((lane >> 3) & 1));
                uint32_t vh4[4], vl4[4];
                ldmatrix_x4(vh4, va);
                ldmatrix_x4(vl4, va + AT_B);
                mma_bf16(O[2 * jj],     ph4, vh4);
                mma_bf16(O[2 * jj],     pl4, vh4);
                mma_bf16(O[2 * jj],     ph4, vl4);
                mma_bf16(O[2 * jj + 1], ph4, vh4 + 2);
                mma_bf16(O[2 * jj + 1], pl4, vh4 + 2);
                mma_bf16(O[2 * jj + 1], ph4, vl4 + 2);
            }
        }
    }

    // --- Epilogue: ctx hi/lo to [b*SEQ+s][DMODEL] ---
    const float inv0 = 1.0f / l0;
    const float inv1 = 1.0f / l1;
    const int b    = bh >> 4;
    const int head = bh & 15;
    const int r0   = qBase + rl0;
    #pragma unroll
    for (int j = 0; j < 8; j++) {
        const int col = head * HDIM + 8 * j + c0;
        const size_t i0 = (size_t)(b * SEQ + r0) * DMODEL + col;
        const size_t i1 = (size_t)(b * SEQ + r0 + 8) * DMODEL + col;
        __nv_bfloat162 hv, lv;
        split2(O[j][0] * inv0, hv.x, lv.x);
        split2(O[j][1] * inv0, hv.y, lv.y);
        *reinterpret_cast<__nv_bfloat162*>(g_ch + i0) = hv;
        *reinterpret_cast<__nv_bfloat162*>(g_cl + i0) = lv;
        split2(O[j][2] * inv1, hv.x, lv.x);
        split2(O[j][3] * inv1, hv.y, lv.y);
        *reinterpret_cast<__nv_bfloat162*>(g_ch + i1) = hv;
        *reinterpret_cast<__nv_bfloat162*>(g_cl + i1) = lv;
    }
}

// ---------------------------------------------------------------------------
// Launch
// ---------------------------------------------------------------------------
extern "C" void kernel_launch(void* const* d_in, const int* in_sizes, int n_in,
                              void* d_out, int out_size)
{
    const float* x  = (const float*)d_in[0];
    const float* wq = (const float*)d_in[1];
    const float* bq = (const float*)d_in[2];
    const float* wk = (const float*)d_in[3];
    const float* bk = (const float*)d_in[4];
    const float* wv = (const float*)d_in[5];
    const float* bv = (const float*)d_in[6];
    const float* wo = (const float*)d_in[7];
    const float* bo = (const float*)d_in[8];
    float* out = (float*)d_out;

    __nv_bfloat16 *xh, *xl, *wh, *wl, *qh, *ql, *kh, *kl, *vh, *vl, *ch, *cl;
    cudaGetSymbolAddress((void**)&xh, g_xh);
    cudaGetSymbolAddress((void**)&xl, g_xl);
    cudaGetSymbolAddress((void**)&wh, g_wh);
    cudaGetSymbolAddress((void**)&wl, g_wl);
    cudaGetSymbolAddress((void**)&qh, g_qh);
    cudaGetSymbolAddress((void**)&ql, g_ql);
    cudaGetSymbolAddress((void**)&kh, g_kh);
    cudaGetSymbolAddress((void**)&kl, g_kl);
    cudaGetSymbolAddress((void**)&vh, g_vh);
    cudaGetSymbolAddress((void**)&vl, g_vl);
    cudaGetSymbolAddress((void**)&ch, g_ch);
    cudaGetSymbolAddress((void**)&cl, g_cl);

    const int NX = MROWS * DMODEL;
    const int NW = DMODEL * DMODEL;
    const float* wsrc[4] = {wq, wk, wv, wo};

    split_bf16_kernel<<<NX / 4 / 256, 256>>>(x, xh, xl, NX);
    for (int i = 0; i < 4; i++)
        split_bf16_kernel<<<NW / 4 / 256, 256>>>(wsrc[i], wh + (size_t)i * NW,
                                                 wl + (size_t)i * NW, NW);

    cudaFuncSetAttribute(mma_gemm_qkv, cudaFuncAttributeMaxDynamicSharedMemorySize, GEMM_SMEM);
    cudaFuncSetAttribute(mma_gemm_out, cudaFuncAttributeMaxDynamicSharedMemorySize, GEMM_SMEM);
    cudaFuncSetAttribute(attn_mma_kernel, cudaFuncAttributeMaxDynamicSharedMemorySize, ATTN_SMEM);

    // Merged Q/K/V projections: grid (24, 32)
    dim3 qkvGrid(24, MROWS / 128);
    mma_gemm_qkv<<<qkvGrid, 256, GEMM_SMEM>>>(xh, xl, wh, wl, bq, bk, bv,
                                              qh, ql, kh, kl, vh, vl);

    // Tensor-core flash attention: 128-row q tiles
    dim3 attnGrid(SEQ / 128, BATCH * NHEAD);
    attn_mma_kernel<<<attnGrid, 256, ATTN_SMEM>>>();

    // Output projection (fp32 out)
    dim3 gemmGrid(DMODEL / 128, MROWS / 128);
    mma_gemm_out<<<gemmGrid, 256, GEMM_SMEM>>>(ch, cl, wh + 3 * (size_t)NW, wl + 3 * (size_t)NW,
                                               bo, out);
}

// round 8
// speedup vs baseline: 1.1228x; 1.1228x over previous
#include <cuda_runtime.h>
#include <cuda_bf16.h>
#include <cuda_fp16.h>
#include <cstdint>

#define BATCH  2
#define SEQ    2048
#define DMODEL 1024
#define NHEAD  16
#define HDIM   64
#define MROWS  (BATCH * SEQ)       // 4096

// ---------------------------------------------------------------------------
// Scratch (allocation-free rule: __device__ globals)
// ---------------------------------------------------------------------------
__device__ __nv_bfloat16 g_xh[MROWS * DMODEL];      // x split hi/lo (bf16)
__device__ __nv_bfloat16 g_xl[MROWS * DMODEL];
__device__ __nv_bfloat16 g_wh[4][DMODEL * DMODEL];  // wq,wk,wv,wo hi
__device__ __nv_bfloat16 g_wl[4][DMODEL * DMODEL];  // wq,wk,wv,wo lo
// q split fp16 hi/lo, [bh][s][hd], pre-scaled by 0.125
__device__ __half g_qh[MROWS * DMODEL];
__device__ __half g_ql[MROWS * DMODEL];
// k single fp16, [bh][s][hd]
__device__ __half g_kf[MROWS * DMODEL];
// v single fp16 TRANSPOSED: [bh][hd][s]
__device__ __half g_vf[MROWS * DMODEL];
// ctx split bf16, [b*s][d]
__device__ __nv_bfloat16 g_ch[MROWS * DMODEL];
__device__ __nv_bfloat16 g_cl[MROWS * DMODEL];

// ---------------------------------------------------------------------------
// Warp-MMA + cp.async helpers (base compute_103 PTX)
// ---------------------------------------------------------------------------
__device__ __forceinline__ uint32_t smem_u32(const void* p) {
    uint32_t a;
    asm("{ .reg .u64 t; cvta.to.shared.u64 t, %1; cvt.u32.u64 %0, t; }"
        : "=r"(a) : "l"(p));
    return a;
}

__device__ __forceinline__ void ldmatrix_x4(uint32_t* r, uint32_t addr) {
    asm volatile("ldmatrix.sync.aligned.m8n8.x4.shared.b16 {%0,%1,%2,%3}, [%4];"
                 : "=r"(r[0]), "=r"(r[1]), "=r"(r[2]), "=r"(r[3]) : "r"(addr));
}

__device__ __forceinline__ void mma_bf16(float* c, const uint32_t* a, const uint32_t* b) {
    asm volatile(
        "mma.sync.aligned.m16n8k16.row.col.f32.bf16.bf16.f32 "
        "{%0,%1,%2,%3}, {%4,%5,%6,%7}, {%8,%9}, {%0,%1,%2,%3};"
        : "+f"(c[0]), "+f"(c[1]), "+f"(c[2]), "+f"(c[3])
        : "r"(a[0]), "r"(a[1]), "r"(a[2]), "r"(a[3]), "r"(b[0]), "r"(b[1]));
}

__device__ __forceinline__ void mma_f16(float* c, const uint32_t* a, const uint32_t* b) {
    asm volatile(
        "mma.sync.aligned.m16n8k16.row.col.f32.f16.f16.f32 "
        "{%0,%1,%2,%3}, {%4,%5,%6,%7}, {%8,%9}, {%0,%1,%2,%3};"
        : "+f"(c[0]), "+f"(c[1]), "+f"(c[2]), "+f"(c[3])
        : "r"(a[0]), "r"(a[1]), "r"(a[2]), "r"(a[3]), "r"(b[0]), "r"(b[1]));
}

__device__ __forceinline__ void cp_async16(uint32_t dst, const void* src) {
    asm volatile("cp.async.cg.shared.global [%0], [%1], 16;" :: "r"(dst), "l"(src));
}
#define CP_COMMIT() asm volatile("cp.async.commit_group;" ::: "memory")
#define CP_WAIT0()  asm volatile("cp.async.wait_group 0;" ::: "memory")

__device__ __forceinline__ void split2(float v, __nv_bfloat16& h, __nv_bfloat16& l) {
    h = __float2bfloat16(v);
    l = __float2bfloat16(v - __bfloat162float(h));
}

__device__ __forceinline__ void split2h(float v, __half& h, __half& l) {
    h = __float2half(v);
    l = __float2half(v - __half2float(h));
}

// ---------------------------------------------------------------------------
// fp32 -> (bf16 hi, bf16 lo) split (x and weights only)
// ---------------------------------------------------------------------------
__global__ __launch_bounds__(256)
void split_bf16_kernel(const float* __restrict__ in,
                       __nv_bfloat16* __restrict__ hi,
                       __nv_bfloat16* __restrict__ lo, int n)
{
    int i4 = (blockIdx.x * blockDim.x + threadIdx.x) * 4;
    if (i4 >= n) return;
    float4 f = *reinterpret_cast<const float4*>(in + i4);
    float fs[4] = {f.x, f.y, f.z, f.w};
    __nv_bfloat162 hv[2], lv[2];
    #pragma unroll
    for (int j = 0; j < 2; j++) {
        __nv_bfloat16 h0, h1, l0, l1;
        split2(fs[2 * j], h0, l0);
        split2(fs[2 * j + 1], h1, l1);
        hv[j].x = h0; hv[j].y = h1;
        lv[j].x = l0; lv[j].y = l1;
    }
    *reinterpret_cast<__nv_bfloat162*>(hi + i4)     = hv[0];
    *reinterpret_cast<__nv_bfloat162*>(hi + i4 + 2) = hv[1];
    *reinterpret_cast<__nv_bfloat162*>(lo + i4)     = lv[0];
    *reinterpret_cast<__nv_bfloat162*>(lo + i4 + 2) = lv[1];
}

// ---------------------------------------------------------------------------
// GEMM tiling constants
// CTA 128x128 tile, 8 warps (2x4), warp tile 64x32, K-chunk 64, 2 stages.
// ---------------------------------------------------------------------------
#define LDT       72
#define TILE_ELEM (128 * LDT)
#define TILE_B    (TILE_ELEM * 2)        // 18432 bytes
#define STAGE_B   (4 * TILE_B)           // 73728 bytes
#define GEMM_SMEM (2 * STAGE_B)          // 147456 bytes

// ---------------------------------------------------------------------------
// Merged QKV GEMM: grid (24, 32); which = blockIdx.x>>3 selects wq/wk/wv.
// which 0 -> q fp16 hi/lo [bh][s][hd], scaled 0.125
// which 1 -> k single fp16 [bh][s][hd]
// which 2 -> v single fp16 TRANSPOSED [bh][hd][s]
// ---------------------------------------------------------------------------
__global__ __launch_bounds__(256)
void mma_gemm_qkv(const __nv_bfloat16* __restrict__ xh,
                  const __nv_bfloat16* __restrict__ xl,
                  const __nv_bfloat16* __restrict__ wh,
                  const __nv_bfloat16* __restrict__ wl,
                  const float* __restrict__ bq,
                  const float* __restrict__ bk,
                  const float* __restrict__ bv,
                  __half* __restrict__ qh,
                  __half* __restrict__ ql,
                  __half* __restrict__ kf,
                  __half* __restrict__ vf)
{
    extern __shared__ __align__(16) char smem[];
    const uint32_t sbase = smem_u32(smem);

    const int tid  = threadIdx.x;
    const int wid  = tid >> 5;
    const int lane = tid & 31;
    const int which = blockIdx.x >> 3;
    const int nBase = (blockIdx.x & 7) * 128;
    const int mBase = blockIdx.y * 128;
    const int warp_m = (wid >> 2) * 64;
    const int warp_n = (wid & 3) * 32;

    const size_t NW = (size_t)DMODEL * DMODEL;
    const __nv_bfloat16* Bh = wh + which * NW;
    const __nv_bfloat16* Bl = wl + which * NW;
    const float* bias = (which == 0) ? bq : (which == 1) ? bk : bv;
    const float scale = (which == 0) ? 0.125f : 1.0f;
    const __nv_bfloat16* srcs[4] = {xh, xl, Bh, Bl};

    auto stage = [&](uint32_t sdst, int kc) {
        #pragma unroll
        for (int t = 0; t < 4; t++) {
            const __nv_bfloat16* src = srcs[t];
            const int rb = (t < 2) ? mBase : nBase;
            #pragma unroll
            for (int it = 0; it < 4; it++) {
                const int slot = tid + it * 256;
                const int row  = slot >> 3;
                const int c8   = slot & 7;
                cp_async16(sdst + t * TILE_B + 2 * (uint32_t)(row * LDT + c8 * 8),
                           src + (size_t)(rb + row) * DMODEL + kc + c8 * 8);
            }
        }
    };

    float acc[4][4][4];
    #pragma unroll
    for (int mi = 0; mi < 4; mi++)
        #pragma unroll
        for (int ni = 0; ni < 4; ni++)
            #pragma unroll
            for (int e = 0; e < 4; e++) acc[mi][ni][e] = 0.0f;

    const uint32_t aRow = (uint32_t)(warp_m + (lane & 15)) * LDT + (lane >> 4) * 8;
    const uint32_t bRow = (uint32_t)(warp_n + 8 * (lane >> 4) + (lane & 7)) * LDT
                          + 8 * ((lane >> 3) & 1);

    stage(sbase, 0);
    CP_COMMIT();

    int cur = 0;
    for (int kc = 0; kc < DMODEL; kc += 64) {
        CP_WAIT0();
        __syncthreads();
        if (kc + 64 < DMODEL) {
            stage(sbase + (uint32_t)((cur ^ 1) * STAGE_B), kc + 64);
            CP_COMMIT();
        }

        const uint32_t uA = sbase + (uint32_t)(cur * STAGE_B) + 2 * aRow;
        const uint32_t uB = sbase + (uint32_t)(cur * STAGE_B + 2 * TILE_B) + 2 * bRow;

        #pragma unroll
        for (int ks = 0; ks < 4; ks++) {
            const uint32_t kOff = 2 * (uint32_t)(ks * 16);
            uint32_t ah[4][4], al[4][4], bh4[2][4], bl4[2][4];
            #pragma unroll
            for (int mi = 0; mi < 4; mi++) {
                const uint32_t addr = uA + kOff + 2 * (uint32_t)(mi * 16) * LDT;
                ldmatrix_x4(ah[mi], addr);
                ldmatrix_x4(al[mi], addr + TILE_B);
            }
            #pragma unroll
            for (int np = 0; np < 2; np++) {
                const uint32_t addr = uB + kOff + 2 * (uint32_t)(np * 16) * LDT;
                ldmatrix_x4(bh4[np], addr);
                ldmatrix_x4(bl4[np], addr + TILE_B);
            }
            #pragma unroll
            for (int mi = 0; mi < 4; mi++)
                #pragma unroll
                for (int ni = 0; ni < 4; ni++) {
                    const uint32_t* bh = &bh4[ni >> 1][2 * (ni & 1)];
                    const uint32_t* bl = &bl4[ni >> 1][2 * (ni & 1)];
                    mma_bf16(acc[mi][ni], ah[mi], bh);
                    mma_bf16(acc[mi][ni], al[mi], bh);
                    mma_bf16(acc[mi][ni], ah[mi], bl);
                }
        }
        cur ^= 1;
    }

    const int rBase = mBase + warp_m + (lane >> 2);
    const int cBase = nBase + warp_n + (lane & 3) * 2;
    #pragma unroll
    for (int mi = 0; mi < 4; mi++) {
        #pragma unroll
        for (int ni = 0; ni < 4; ni++) {
            #pragma unroll
            for (int half = 0; half < 2; half++) {
                const int m = rBase + mi * 16 + half * 8;
                const int n = cBase + ni * 8;
                const float v0 = (acc[mi][ni][half * 2]     + bias[n])     * scale;
                const float v1 = (acc[mi][ni][half * 2 + 1] + bias[n + 1]) * scale;
                const int b  = m >> 11;
                const int s  = m & 2047;
                const int h  = n >> 6;
                const int hd = n & 63;
                if (which == 0) {
                    const size_t idx = (((size_t)(b * NHEAD + h) * SEQ) + s) * HDIM + hd;
                    __half h0, l0, h1, l1;
                    split2h(v0, h0, l0);
                    split2h(v1, h1, l1);
                    *reinterpret_cast<__half2*>(qh + idx) = __halves2half2(h0, h1);
                    *reinterpret_cast<__half2*>(ql + idx) = __halves2half2(l0, l1);
                } else if (which == 1) {
                    const size_t idx = (((size_t)(b * NHEAD + h) * SEQ) + s) * HDIM + hd;
                    *reinterpret_cast<__half2*>(kf + idx) =
                        __halves2half2(__float2half(v0), __float2half(v1));
                } else {
                    const size_t idx = (((size_t)(b * NHEAD + h) * HDIM) + hd) * SEQ + s;
                    vf[idx]       = __float2half(v0);
                    vf[idx + SEQ] = __float2half(v1);
                }
            }
        }
    }
}

// ---------------------------------------------------------------------------
// Output-projection GEMM (fp32 out), bf16 3-term.
// ---------------------------------------------------------------------------
__global__ __launch_bounds__(256)
void mma_gemm_out(const __nv_bfloat16* __restrict__ Ah,
                  const __nv_bfloat16* __restrict__ Al,
                  const __nv_bfloat16* __restrict__ Bh,
                  const __nv_bfloat16* __restrict__ Bl,
                  const float* __restrict__ bias,
                  float* __restrict__ out)
{
    extern __shared__ __align__(16) char smem[];
    const uint32_t sbase = smem_u32(smem);

    const int tid  = threadIdx.x;
    const int wid  = tid >> 5;
    const int lane = tid & 31;
    const int mBase = blockIdx.y * 128;
    const int nBase = blockIdx.x * 128;
    const int warp_m = (wid >> 2) * 64;
    const int warp_n = (wid & 3) * 32;

    const __nv_bfloat16* srcs[4] = {Ah, Al, Bh, Bl};

    auto stage = [&](uint32_t sdst, int kc) {
        #pragma unroll
        for (int t = 0; t < 4; t++) {
            const __nv_bfloat16* src = srcs[t];
            const int rb = (t < 2) ? mBase : nBase;
            #pragma unroll
            for (int it = 0; it < 4; it++) {
                const int slot = tid + it * 256;
                const int row  = slot >> 3;
                const int c8   = slot & 7;
                cp_async16(sdst + t * TILE_B + 2 * (uint32_t)(row * LDT + c8 * 8),
                           src + (size_t)(rb + row) * DMODEL + kc + c8 * 8);
            }
        }
    };

    float acc[4][4][4];
    #pragma unroll
    for (int mi = 0; mi < 4; mi++)
        #pragma unroll
        for (int ni = 0; ni < 4; ni++)
            #pragma unroll
            for (int e = 0; e < 4; e++) acc[mi][ni][e] = 0.0f;

    const uint32_t aRow = (uint32_t)(warp_m + (lane & 15)) * LDT + (lane >> 4) * 8;
    const uint32_t bRow = (uint32_t)(warp_n + 8 * (lane >> 4) + (lane & 7)) * LDT
                          + 8 * ((lane >> 3) & 1);

    stage(sbase, 0);
    CP_COMMIT();

    int cur = 0;
    for (int kc = 0; kc < DMODEL; kc += 64) {
        CP_WAIT0();
        __syncthreads();
        if (kc + 64 < DMODEL) {
            stage(sbase + (uint32_t)((cur ^ 1) * STAGE_B), kc + 64);
            CP_COMMIT();
        }

        const uint32_t uA = sbase + (uint32_t)(cur * STAGE_B) + 2 * aRow;
        const uint32_t uB = sbase + (uint32_t)(cur * STAGE_B + 2 * TILE_B) + 2 * bRow;

        #pragma unroll
        for (int ks = 0; ks < 4; ks++) {
            const uint32_t kOff = 2 * (uint32_t)(ks * 16);
            uint32_t ah[4][4], al[4][4], bh4[2][4], bl4[2][4];
            #pragma unroll
            for (int mi = 0; mi < 4; mi++) {
                const uint32_t addr = uA + kOff + 2 * (uint32_t)(mi * 16) * LDT;
                ldmatrix_x4(ah[mi], addr);
                ldmatrix_x4(al[mi], addr + TILE_B);
            }
            #pragma unroll
            for (int np = 0; np < 2; np++) {
                const uint32_t addr = uB + kOff + 2 * (uint32_t)(np * 16) * LDT;
                ldmatrix_x4(bh4[np], addr);
                ldmatrix_x4(bl4[np], addr + TILE_B);
            }
            #pragma unroll
            for (int mi = 0; mi < 4; mi++)
                #pragma unroll
                for (int ni = 0; ni < 4; ni++) {
                    const uint32_t* bh = &bh4[ni >> 1][2 * (ni & 1)];
                    const uint32_t* bl = &bl4[ni >> 1][2 * (ni & 1)];
                    mma_bf16(acc[mi][ni], ah[mi], bh);
                    mma_bf16(acc[mi][ni], al[mi], bh);
                    mma_bf16(acc[mi][ni], ah[mi], bl);
                }
        }
        cur ^= 1;
    }

    const int rBase = mBase + warp_m + (lane >> 2);
    const int cBase = nBase + warp_n + (lane & 3) * 2;
    #pragma unroll
    for (int mi = 0; mi < 4; mi++) {
        #pragma unroll
        for (int ni = 0; ni < 4; ni++) {
            #pragma unroll
            for (int half = 0; half < 2; half++) {
                const int m = rBase + mi * 16 + half * 8;
                const int n = cBase + ni * 8;
                out[(size_t)m * DMODEL + n]     = acc[mi][ni][half * 2]     + bias[n];
                out[(size_t)m * DMODEL + n + 1] = acc[mi][ni][half * 2 + 1] + bias[n + 1];
            }
        }
    }
}

// ---------------------------------------------------------------------------
// Tensor-core flash attention (causal), fp16 asymmetric 2-term.
// q-tile 128 rows, 256 threads (8 warps; warp owns 16 q-rows), k-tile 64.
// grid = (SEQ/128, BATCH*NHEAD). Q fp16 hi/lo (pre-scaled 0.125);
// K single fp16 [bh][s][hd]; V single fp16 transposed [bh][hd][s].
// Smem: stage s at s*18432 {Kf, Vf each 64x72 fp16}; P (128x72 hi/lo) at 36864.
// ---------------------------------------------------------------------------
#define ALDT   72
#define KT_B   9216                        // 64x72 fp16 tile, bytes
#define AST_B  (2 * KT_B)                  // 18432
#define P_OFF  (2 * AST_B)                 // 36864
#define PT_B   (128 * ALDT * 2)            // 18432 (128x72 fp16)
#define ATTN_SMEM (P_OFF + 2 * PT_B)       // 73728

__global__ __launch_bounds__(256)
void attn_mma_kernel()
{
    extern __shared__ __align__(16) char asmem[];
    const uint32_t abase = smem_u32(asmem);

    const int tid  = threadIdx.x;
    const int w    = tid >> 5;
    const int lane = tid & 31;
    const int qi   = gridDim.x - 1 - blockIdx.x;    // long CTAs first
    const int bh   = blockIdx.y;
    const int qBase = qi * 128;
    const int nkt  = 2 * qi + 2;
    const size_t hOff = (size_t)bh * SEQ * HDIM;    // q,k: [bh][s][hd]
    const size_t vOff = (size_t)bh * HDIM * SEQ;    // v^T: [bh][hd][s]

    // K/V stage loader: 64 rows x 8 chunks x 2 arrays / 256 thr = 4 cp.async
    auto stageKV = [&](uint32_t su, int kBase) {
        #pragma unroll
        for (int it = 0; it < 2; it++) {
            const int slot = tid + it * 256;          // 0..511
            const int row = slot >> 3, c8 = slot & 7;
            const uint32_t so = 2 * (uint32_t)(row * ALDT + c8 * 8);
            cp_async16(su + so,        g_kf + hOff + (size_t)(kBase + row) * HDIM + c8 * 8);
            cp_async16(su + KT_B + so, g_vf + vOff + (size_t)row * SEQ + kBase + c8 * 8);
        }
    };

    stageKV(abase, 0);
    CP_COMMIT();

    // Stage Q (128x64 fp16 hi/lo) through P buffers; pull A-frags to registers
    {
        __half* sPh = reinterpret_cast<__half*>(asmem + P_OFF);
        __half* sPl = reinterpret_cast<__half*>(asmem + P_OFF + PT_B);
        #pragma unroll
        for (int it = 0; it < 4; it++) {
            const int slot = tid + it * 256;          // 0..1023
            const int row = slot >> 3, c8 = slot & 7;
            const size_t g = hOff + (size_t)(qBase + row) * HDIM + c8 * 8;
            *reinterpret_cast<uint4*>(sPh + row * ALDT + c8 * 8) =
                *reinterpret_cast<const uint4*>(g_qh + g);
            *reinterpret_cast<uint4*>(sPl + row * ALDT + c8 * 8) =
                *reinterpret_cast<const uint4*>(g_ql + g);
        }
    }
    __syncthreads();

    uint32_t qh[4][4], ql[4][4];
    {
        const uint32_t qa = abase + P_OFF +
            2 * ((uint32_t)(w * 16 + (lane & 15)) * ALDT + (lane >> 4) * 8);
        #pragma unroll
        for (int t = 0; t < 4; t++) {
            ldmatrix_x4(qh[t], qa + 32 * t);
            ldmatrix_x4(ql[t], qa + PT_B + 32 * t);
        }
    }

    float O[8][4];
    #pragma unroll
    for (int j = 0; j < 8; j++)
        #pragma unroll
        for (int e = 0; e < 4; e++) O[j][e] = 0.0f;
    float m0 = -1e30f, m1 = -1e30f, l0 = 0.0f, l1 = 0.0f;

    const int rl0 = w * 16 + (lane >> 2);       // local row (0..127)
    const int c0  = 2 * (lane & 3);
    const uint32_t pa = abase + P_OFF +
        2 * ((uint32_t)(w * 16 + (lane & 15)) * ALDT + (lane >> 4) * 8);

    int cur = 0;
    for (int kt = 0; kt < nkt; kt++) {
        const int kBase = kt * 64;
        CP_WAIT0();
        __syncthreads();
        if (kt + 1 < nkt) {
            stageKV(abase + (uint32_t)((cur ^ 1) * AST_B), (kt + 1) * 64);
            CP_COMMIT();
        }
        const uint32_t uK = abase + (uint32_t)(cur * AST_B);
        const uint32_t uV = uK + KT_B;
        cur ^= 1;

        const int d = kBase - qBase;            // k-col offset vs local rows
        if (d > w * 16 + 15) continue;          // warp fully masked (no CTA barriers below)

        // --- S = (Qh + Ql) K, single-fp16 K, x4 B loads (frag pairs) ---
        float s[8][4];
        #pragma unroll
        for (int j = 0; j < 8; j++)
            #pragma unroll
            for (int e = 0; e < 4; e++) s[j][e] = 0.0f;

        #pragma unroll
        for (int t = 0; t < 4; t++) {
            #pragma unroll
            for (int jj = 0; jj < 4; jj++) {
                const uint32_t ba = uK + 2 * ((uint32_t)(16 * jj + 8 * (lane >> 4) + (lane & 7)) * ALDT
                                              + 16 * t + 8 * ((lane >> 3) & 1));
                uint32_t kf4[4];
                ldmatrix_x4(kf4, ba);
                mma_f16(s[2 * jj],     qh[t], kf4);
                mma_f16(s[2 * jj],     ql[t], kf4);
                mma_f16(s[2 * jj + 1], qh[t], kf4 + 2);
                mma_f16(s[2 * jj + 1], ql[t], kf4 + 2);
            }
        }

        // --- Causal mask: col + d > row  (only possible on last two tiles) ---
        if (kt >= nkt - 2) {
            #pragma unroll
            for (int j = 0; j < 8; j++) {
                #pragma unroll
                for (int e = 0; e < 2; e++) {
                    const int col = 8 * j + c0 + e + d;
                    if (col > rl0)     s[j][e]     = -1e30f;
                    if (col > rl0 + 8) s[j][2 + e] = -1e30f;
                }
            }
        }

        // --- Online softmax ---
        float mt0 = -1e30f, mt1 = -1e30f;
        #pragma unroll
        for (int j = 0; j < 8; j++) {
            mt0 = fmaxf(mt0, fmaxf(s[j][0], s[j][1]));
            mt1 = fmaxf(mt1, fmaxf(s[j][2], s[j][3]));
        }
        mt0 = fmaxf(mt0, __shfl_xor_sync(0xffffffffu, mt0, 1));
        mt0 = fmaxf(mt0, __shfl_xor_sync(0xffffffffu, mt0, 2));
        mt1 = fmaxf(mt1, __shfl_xor_sync(0xffffffffu, mt1, 1));
        mt1 = fmaxf(mt1, __shfl_xor_sync(0xffffffffu, mt1, 2));

        const float mn0 = fmaxf(m0, mt0);
        const float mn1 = fmaxf(m1, mt1);
        const float cr0 = __expf(m0 - mn0);
        const float cr1 = __expf(m1 - mn1);
        m0 = mn0; m1 = mn1;

        float ls0 = 0.0f, ls1 = 0.0f;
        #pragma unroll
        for (int j = 0; j < 8; j++) {
            s[j][0] = __expf(s[j][0] - mn0);
            s[j][1] = __expf(s[j][1] - mn0);
            s[j][2] = __expf(s[j][2] - mn1);
            s[j][3] = __expf(s[j][3] - mn1);
            ls0 += s[j][0] + s[j][1];
            ls1 += s[j][2] + s[j][3];
        }
        ls0 += __shfl_xor_sync(0xffffffffu, ls0, 1);
        ls0 += __shfl_xor_sync(0xffffffffu, ls0, 2);
        ls1 += __shfl_xor_sync(0xffffffffu, ls1, 1);
        ls1 += __shfl_xor_sync(0xffffffffu, ls1, 2);
        l0 = l0 * cr0 + ls0;
        l1 = l1 * cr1 + ls1;
        #pragma unroll
        for (int j = 0; j < 8; j++) {
            O[j][0] *= cr0; O[j][1] *= cr0;
            O[j][2] *= cr1; O[j][3] *= cr1;
        }

        // --- Store P (fp16 hi/lo): same-warp rows only ---
        __half* sPh = reinterpret_cast<__half*>(asmem + P_OFF);
        __half* sPl = reinterpret_cast<__half*>(asmem + P_OFF + PT_B);
        #pragma unroll
        for (int j = 0; j < 8; j++) {
            const int col = 8 * j + c0;
            __half h0, l0h, h1, l1h;
            split2h(s[j][0], h0, l0h);
            split2h(s[j][1], h1, l1h);
            *reinterpret_cast<__half2*>(sPh + rl0 * ALDT + col) = __halves2half2(h0, h1);
            *reinterpret_cast<__half2*>(sPl + rl0 * ALDT + col) = __halves2half2(l0h, l1h);
            split2h(s[j][2], h0, l0h);
            split2h(s[j][3], h1, l1h);
            *reinterpret_cast<__half2*>(sPh + (rl0 + 8) * ALDT + col) = __halves2half2(h0, h1);
            *reinterpret_cast<__half2*>(sPl + (rl0 + 8) * ALDT + col) = __halves2half2(l0h, l1h);
        }
        __syncwarp();

        // --- O += (Ph + Pl) V, single-fp16 V (x4 loads, frag pairs) ---
        #pragma unroll
        for (int t = 0; t < 4; t++) {
            uint32_t ph4[4], pl4[4];
            ldmatrix_x4(ph4, pa + 32 * t);
            ldmatrix_x4(pl4, pa + PT_B + 32 * t);
            #pragma unroll
            for (int jj = 0; jj < 4; jj++) {
                const uint32_t va = uV + 2 * ((uint32_t)(16 * jj + 8 * (lane >> 4) + (lane & 7)) * ALDT
                                              + 16 * t + 8 * ((lane >> 3) & 1));
                uint32_t vf4[4];
                ldmatrix_x4(vf4, va);
                mma_f16(O[2 * jj],     ph4, vf4);
                mma_f16(O[2 * jj],     pl4, vf4);
                mma_f16(O[2 * jj + 1], ph4, vf4 + 2);
                mma_f16(O[2 * jj + 1], pl4, vf4 + 2);
            }
        }
    }

    // --- Epilogue: ctx bf16 hi/lo to [b*SEQ+s][DMODEL] ---
    const float inv0 = 1.0f / l0;
    const float inv1 = 1.0f / l1;
    const int b    = bh >> 4;
    const int head = bh & 15;
    const int r0   = qBase + rl0;
    #pragma unroll
    for (int j = 0; j < 8; j++) {
        const int col = head * HDIM + 8 * j + c0;
        const size_t i0 = (size_t)(b * SEQ + r0) * DMODEL + col;
        const size_t i1 = (size_t)(b * SEQ + r0 + 8) * DMODEL + col;
        __nv_bfloat162 hv, lv;
        split2(O[j][0] * inv0, hv.x, lv.x);
        split2(O[j][1] * inv0, hv.y, lv.y);
        *reinterpret_cast<__nv_bfloat162*>(g_ch + i0) = hv;
        *reinterpret_cast<__nv_bfloat162*>(g_cl + i0) = lv;
        split2(O[j][2] * inv1, hv.x, lv.x);
        split2(O[j][3] * inv1, hv.y, lv.y);
        *reinterpret_cast<__nv_bfloat162*>(g_ch + i1) = hv;
        *reinterpret_cast<__nv_bfloat162*>(g_cl + i1) = lv;
    }
}

// ---------------------------------------------------------------------------
// Launch
// ---------------------------------------------------------------------------
extern "C" void kernel_launch(void* const* d_in, const int* in_sizes, int n_in,
                              void* d_out, int out_size)
{
    const float* x  = (const float*)d_in[0];
    const float* wq = (const float*)d_in[1];
    const float* bq = (const float*)d_in[2];
    const float* wk = (const float*)d_in[3];
    const float* bk = (const float*)d_in[4];
    const float* wv = (const float*)d_in[5];
    const float* bv = (const float*)d_in[6];
    const float* wo = (const float*)d_in[7];
    const float* bo = (const float*)d_in[8];
    float* out = (float*)d_out;

    __nv_bfloat16 *xh, *xl, *wh, *wl, *ch, *cl;
    __half *qh, *ql, *kf, *vf;
    cudaGetSymbolAddress((void**)&xh, g_xh);
    cudaGetSymbolAddress((void**)&xl, g_xl);
    cudaGetSymbolAddress((void**)&wh, g_wh);
    cudaGetSymbolAddress((void**)&wl, g_wl);
    cudaGetSymbolAddress((void**)&qh, g_qh);
    cudaGetSymbolAddress((void**)&ql, g_ql);
    cudaGetSymbolAddress((void**)&kf, g_kf);
    cudaGetSymbolAddress((void**)&vf, g_vf);
    cudaGetSymbolAddress((void**)&ch, g_ch);
    cudaGetSymbolAddress((void**)&cl, g_cl);

    const int NX = MROWS * DMODEL;
    const int NW = DMODEL * DMODEL;
    const float* wsrc[4] = {wq, wk, wv, wo};

    split_bf16_kernel<<<NX / 4 / 256, 256>>>(x, xh, xl, NX);
    for (int i = 0; i < 4; i++)
        split_bf16_kernel<<<NW / 4 / 256, 256>>>(wsrc[i], wh + (size_t)i * NW,
                                                 wl + (size_t)i * NW, NW);

    cudaFuncSetAttribute(mma_gemm_qkv, cudaFuncAttributeMaxDynamicSharedMemorySize, GEMM_SMEM);
    cudaFuncSetAttribute(mma_gemm_out, cudaFuncAttributeMaxDynamicSharedMemorySize, GEMM_SMEM);
    cudaFuncSetAttribute(attn_mma_kernel, cudaFuncAttributeMaxDynamicSharedMemorySize, ATTN_SMEM);

    // Merged Q/K/V projections: grid (24, 32)
    dim3 qkvGrid(24, MROWS / 128);
    mma_gemm_qkv<<<qkvGrid, 256, GEMM_SMEM>>>(xh, xl, wh, wl, bq, bk, bv,
                                              qh, ql, kf, vf);

    // Tensor-core flash attention (fp16 2-term): 128-row q tiles
    dim3 attnGrid(SEQ / 128, BATCH * NHEAD);
    attn_mma_kernel<<<attnGrid, 256, ATTN_SMEM>>>();

    // Output projection (fp32 out)
    dim3 gemmGrid(DMODEL / 128, MROWS / 128);
    mma_gemm_out<<<gemmGrid, 256, GEMM_SMEM>>>(ch, cl, wh + 3 * (size_t)NW, wl + 3 * (size_t)NW,
                                               bo, out);
}

// round 9
// speedup vs baseline: 1.4641x; 1.3040x over previous
#include <cuda_runtime.h>
#include <cuda_bf16.h>
#include <cuda_fp16.h>
#include <cstdint>

#define BATCH  2
#define SEQ    2048
#define DMODEL 1024
#define NHEAD  16
#define HDIM   64
#define MROWS  (BATCH * SEQ)       // 4096

// ---------------------------------------------------------------------------
// Scratch (allocation-free rule: __device__ globals)
// ---------------------------------------------------------------------------
__device__ __half g_xh[MROWS * DMODEL];       // x split fp16 hi/lo
__device__ __half g_xl[MROWS * DMODEL];
__device__ __half g_wf[4][DMODEL * DMODEL];   // wq,wk,wv,wo single fp16
// q split fp16 hi/lo, [bh][s][hd], pre-scaled by 0.125
__device__ __half g_qh[MROWS * DMODEL];
__device__ __half g_ql[MROWS * DMODEL];
// k single fp16, [bh][s][hd]
__device__ __half g_kf[MROWS * DMODEL];
// v single fp16 TRANSPOSED: [bh][hd][s]
__device__ __half g_vf[MROWS * DMODEL];
// ctx split fp16, [b*s][d]
__device__ __half g_ch[MROWS * DMODEL];
__device__ __half g_cl[MROWS * DMODEL];

// ---------------------------------------------------------------------------
// Warp-MMA + cp.async helpers (base compute_103 PTX)
// ---------------------------------------------------------------------------
__device__ __forceinline__ uint32_t smem_u32(const void* p) {
    uint32_t a;
    asm("{ .reg .u64 t; cvta.to.shared.u64 t, %1; cvt.u32.u64 %0, t; }"
        : "=r"(a) : "l"(p));
    return a;
}

__device__ __forceinline__ void ldmatrix_x4(uint32_t* r, uint32_t addr) {
    asm volatile("ldmatrix.sync.aligned.m8n8.x4.shared.b16 {%0,%1,%2,%3}, [%4];"
                 : "=r"(r[0]), "=r"(r[1]), "=r"(r[2]), "=r"(r[3]) : "r"(addr));
}

__device__ __forceinline__ void mma_f16(float* c, const uint32_t* a, const uint32_t* b) {
    asm volatile(
        "mma.sync.aligned.m16n8k16.row.col.f32.f16.f16.f32 "
        "{%0,%1,%2,%3}, {%4,%5,%6,%7}, {%8,%9}, {%0,%1,%2,%3};"
        : "+f"(c[0]), "+f"(c[1]), "+f"(c[2]), "+f"(c[3])
        : "r"(a[0]), "r"(a[1]), "r"(a[2]), "r"(a[3]), "r"(b[0]), "r"(b[1]));
}

__device__ __forceinline__ void cp_async16(uint32_t dst, const void* src) {
    asm volatile("cp.async.cg.shared.global [%0], [%1], 16;" :: "r"(dst), "l"(src));
}
#define CP_COMMIT() asm volatile("cp.async.commit_group;" ::: "memory")
#define CP_WAIT0()  asm volatile("cp.async.wait_group 0;" ::: "memory")

__device__ __forceinline__ void split2h(float v, __half& h, __half& l) {
    h = __float2half(v);
    l = __float2half(v - __half2float(h));
}

// ---------------------------------------------------------------------------
// fp32 -> (fp16 hi, fp16 lo) split
// ---------------------------------------------------------------------------
__global__ __launch_bounds__(256)
void split_f16_kernel(const float* __restrict__ in,
                      __half* __restrict__ hi,
                      __half* __restrict__ lo, int n)
{
    int i4 = (blockIdx.x * blockDim.x + threadIdx.x) * 4;
    if (i4 >= n) return;
    float4 f = *reinterpret_cast<const float4*>(in + i4);
    float fs[4] = {f.x, f.y, f.z, f.w};
    __half2 hv[2], lv[2];
    #pragma unroll
    for (int j = 0; j < 2; j++) {
        __half h0, h1, l0, l1;
        split2h(fs[2 * j], h0, l0);
        split2h(fs[2 * j + 1], h1, l1);
        hv[j] = __halves2half2(h0, h1);
        lv[j] = __halves2half2(l0, l1);
    }
    *reinterpret_cast<__half2*>(hi + i4)     = hv[0];
    *reinterpret_cast<__half2*>(hi + i4 + 2) = hv[1];
    *reinterpret_cast<__half2*>(lo + i4)     = lv[0];
    *reinterpret_cast<__half2*>(lo + i4 + 2) = lv[1];
}

// fp32 -> single fp16 convert (weights)
__global__ __launch_bounds__(256)
void cvt_f16_kernel(const float* __restrict__ in, __half* __restrict__ out, int n)
{
    int i4 = (blockIdx.x * blockDim.x + threadIdx.x) * 4;
    if (i4 >= n) return;
    float4 f = *reinterpret_cast<const float4*>(in + i4);
    *reinterpret_cast<__half2*>(out + i4)     = __halves2half2(__float2half(f.x), __float2half(f.y));
    *reinterpret_cast<__half2*>(out + i4 + 2) = __halves2half2(__float2half(f.z), __float2half(f.w));
}

// ---------------------------------------------------------------------------
// GEMM tiling constants
// CTA 128x128 tile, 8 warps (2x4), warp tile 64x32, K-chunk 64, 2 stages.
// Stage holds 3 tiles: Ah, Al (fp16 hi/lo) + W (single fp16).
// ---------------------------------------------------------------------------
#define LDT       72
#define TILE_ELEM (128 * LDT)
#define TILE_B    (TILE_ELEM * 2)        // 18432 bytes
#define STAGE_B   (3 * TILE_B)           // 55296 bytes
#define GEMM_SMEM (2 * STAGE_B)          // 110592 bytes

// ---------------------------------------------------------------------------
// Merged QKV GEMM: grid (24, 32); which = blockIdx.x>>3 selects wq/wk/wv.
// fp16 asymmetric 2-term: S = (Ah + Al) @ W, fp32 accumulate.
// which 0 -> q fp16 hi/lo [bh][s][hd], scaled 0.125
// which 1 -> k single fp16 [bh][s][hd]
// which 2 -> v single fp16 TRANSPOSED [bh][hd][s]
// ---------------------------------------------------------------------------
__global__ __launch_bounds__(256)
void mma_gemm_qkv(const __half* __restrict__ xh,
                  const __half* __restrict__ xl,
                  const __half* __restrict__ wf,
                  const float* __restrict__ bq,
                  const float* __restrict__ bk,
                  const float* __restrict__ bv,
                  __half* __restrict__ qh,
                  __half* __restrict__ ql,
                  __half* __restrict__ kf,
                  __half* __restrict__ vf)
{
    extern __shared__ __align__(16) char smem[];
    const uint32_t sbase = smem_u32(smem);

    const int tid  = threadIdx.x;
    const int wid  = tid >> 5;
    const int lane = tid & 31;
    const int which = blockIdx.x >> 3;
    const int nBase = (blockIdx.x & 7) * 128;
    const int mBase = blockIdx.y * 128;
    const int warp_m = (wid >> 2) * 64;
    const int warp_n = (wid & 3) * 32;

    const size_t NW = (size_t)DMODEL * DMODEL;
    const __half* W = wf + which * NW;
    const float* bias = (which == 0) ? bq : (which == 1) ? bk : bv;
    const float scale = (which == 0) ? 0.125f : 1.0f;
    const __half* srcs[3] = {xh, xl, W};

    auto stage = [&](uint32_t sdst, int kc) {
        #pragma unroll
        for (int t = 0; t < 3; t++) {
            const __half* src = srcs[t];
            const int rb = (t < 2) ? mBase : nBase;
            #pragma unroll
            for (int it = 0; it < 4; it++) {
                const int slot = tid + it * 256;
                const int row  = slot >> 3;
                const int c8   = slot & 7;
                cp_async16(sdst + t * TILE_B + 2 * (uint32_t)(row * LDT + c8 * 8),
                           src + (size_t)(rb + row) * DMODEL + kc + c8 * 8);
            }
        }
    };

    float acc[4][4][4];
    #pragma unroll
    for (int mi = 0; mi < 4; mi++)
        #pragma unroll
        for (int ni = 0; ni < 4; ni++)
            #pragma unroll
            for (int e = 0; e < 4; e++) acc[mi][ni][e] = 0.0f;

    const uint32_t aRow = (uint32_t)(warp_m + (lane & 15)) * LDT + (lane >> 4) * 8;
    const uint32_t bRow = (uint32_t)(warp_n + 8 * (lane >> 4) + (lane & 7)) * LDT
                          + 8 * ((lane >> 3) & 1);

    stage(sbase, 0);
    CP_COMMIT();

    int cur = 0;
    for (int kc = 0; kc < DMODEL; kc += 64) {
        CP_WAIT0();
        __syncthreads();
        if (kc + 64 < DMODEL) {
            stage(sbase + (uint32_t)((cur ^ 1) * STAGE_B), kc + 64);
            CP_COMMIT();
        }

        const uint32_t uA = sbase + (uint32_t)(cur * STAGE_B) + 2 * aRow;
        const uint32_t uB = sbase + (uint32_t)(cur * STAGE_B + 2 * TILE_B) + 2 * bRow;

        #pragma unroll
        for (int ks = 0; ks < 4; ks++) {
            const uint32_t kOff = 2 * (uint32_t)(ks * 16);
            uint32_t ah[4][4], al[4][4], w4[2][4];
            #pragma unroll
            for (int mi = 0; mi < 4; mi++) {
                const uint32_t addr = uA + kOff + 2 * (uint32_t)(mi * 16) * LDT;
                ldmatrix_x4(ah[mi], addr);
                ldmatrix_x4(al[mi], addr + TILE_B);
            }
            #pragma unroll
            for (int np = 0; np < 2; np++) {
                const uint32_t addr = uB + kOff + 2 * (uint32_t)(np * 16) * LDT;
                ldmatrix_x4(w4[np], addr);
            }
            #pragma unroll
            for (int mi = 0; mi < 4; mi++)
                #pragma unroll
                for (int ni = 0; ni < 4; ni++) {
                    const uint32_t* b = &w4[ni >> 1][2 * (ni & 1)];
                    mma_f16(acc[mi][ni], ah[mi], b);
                    mma_f16(acc[mi][ni], al[mi], b);
                }
        }
        cur ^= 1;
    }

    const int rBase = mBase + warp_m + (lane >> 2);
    const int cBase = nBase + warp_n + (lane & 3) * 2;
    #pragma unroll
    for (int mi = 0; mi < 4; mi++) {
        #pragma unroll
        for (int ni = 0; ni < 4; ni++) {
            #pragma unroll
            for (int half = 0; half < 2; half++) {
                const int m = rBase + mi * 16 + half * 8;
                const int n = cBase + ni * 8;
                const float v0 = (acc[mi][ni][half * 2]     + bias[n])     * scale;
                const float v1 = (acc[mi][ni][half * 2 + 1] + bias[n + 1]) * scale;
                const int b  = m >> 11;
                const int s  = m & 2047;
                const int h  = n >> 6;
                const int hd = n & 63;
                if (which == 0) {
                    const size_t idx = (((size_t)(b * NHEAD + h) * SEQ) + s) * HDIM + hd;
                    __half h0, l0, h1, l1;
                    split2h(v0, h0, l0);
                    split2h(v1, h1, l1);
                    *reinterpret_cast<__half2*>(qh + idx) = __halves2half2(h0, h1);
                    *reinterpret_cast<__half2*>(ql + idx) = __halves2half2(l0, l1);
                } else if (which == 1) {
                    const size_t idx = (((size_t)(b * NHEAD + h) * SEQ) + s) * HDIM + hd;
                    *reinterpret_cast<__half2*>(kf + idx) =
                        __halves2half2(__float2half(v0), __float2half(v1));
                } else {
                    const size_t idx = (((size_t)(b * NHEAD + h) * HDIM) + hd) * SEQ + s;
                    vf[idx]       = __float2half(v0);
                    vf[idx + SEQ] = __float2half(v1);
                }
            }
        }
    }
}

// ---------------------------------------------------------------------------
// Output-projection GEMM (fp32 out), fp16 asymmetric 2-term.
// ---------------------------------------------------------------------------
__global__ __launch_bounds__(256)
void mma_gemm_out(const __half* __restrict__ Ah,
                  const __half* __restrict__ Al,
                  const __half* __restrict__ W,
                  const float* __restrict__ bias,
                  float* __restrict__ out)
{
    extern __shared__ __align__(16) char smem[];
    const uint32_t sbase = smem_u32(smem);

    const int tid  = threadIdx.x;
    const int wid  = tid >> 5;
    const int lane = tid & 31;
    const int mBase = blockIdx.y * 128;
    const int nBase = blockIdx.x * 128;
    const int warp_m = (wid >> 2) * 64;
    const int warp_n = (wid & 3) * 32;

    const __half* srcs[3] = {Ah, Al, W};

    auto stage = [&](uint32_t sdst, int kc) {
        #pragma unroll
        for (int t = 0; t < 3; t++) {
            const __half* src = srcs[t];
            const int rb = (t < 2) ? mBase : nBase;
            #pragma unroll
            for (int it = 0; it < 4; it++) {
                const int slot = tid + it * 256;
                const int row  = slot >> 3;
                const int c8   = slot & 7;
                cp_async16(sdst + t * TILE_B + 2 * (uint32_t)(row * LDT + c8 * 8),
                           src + (size_t)(rb + row) * DMODEL + kc + c8 * 8);
            }
        }
    };

    float acc[4][4][4];
    #pragma unroll
    for (int mi = 0; mi < 4; mi++)
        #pragma unroll
        for (int ni = 0; ni < 4; ni++)
            #pragma unroll
            for (int e = 0; e < 4; e++) acc[mi][ni][e] = 0.0f;

    const uint32_t aRow = (uint32_t)(warp_m + (lane & 15)) * LDT + (lane >> 4) * 8;
    const uint32_t bRow = (uint32_t)(warp_n + 8 * (lane >> 4) + (lane & 7)) * LDT
                          + 8 * ((lane >> 3) & 1);

    stage(sbase, 0);
    CP_COMMIT();

    int cur = 0;
    for (int kc = 0; kc < DMODEL; kc += 64) {
        CP_WAIT0();
        __syncthreads();
        if (kc + 64 < DMODEL) {
            stage(sbase + (uint32_t)((cur ^ 1) * STAGE_B), kc + 64);
            CP_COMMIT();
        }

        const uint32_t uA = sbase + (uint32_t)(cur * STAGE_B) + 2 * aRow;
        const uint32_t uB = sbase + (uint32_t)(cur * STAGE_B + 2 * TILE_B) + 2 * bRow;

        #pragma unroll
        for (int ks = 0; ks < 4; ks++) {
            const uint32_t kOff = 2 * (uint32_t)(ks * 16);
            uint32_t ah[4][4], al[4][4], w4[2][4];
            #pragma unroll
            for (int mi = 0; mi < 4; mi++) {
                const uint32_t addr = uA + kOff + 2 * (uint32_t)(mi * 16) * LDT;
                ldmatrix_x4(ah[mi], addr);
                ldmatrix_x4(al[mi], addr + TILE_B);
            }
            #pragma unroll
            for (int np = 0; np < 2; np++) {
                const uint32_t addr = uB + kOff + 2 * (uint32_t)(np * 16) * LDT;
                ldmatrix_x4(w4[np], addr);
            }
            #pragma unroll
            for (int mi = 0; mi < 4; mi++)
                #pragma unroll
                for (int ni = 0; ni < 4; ni++) {
                    const uint32_t* b = &w4[ni >> 1][2 * (ni & 1)];
                    mma_f16(acc[mi][ni], ah[mi], b);
                    mma_f16(acc[mi][ni], al[mi], b);
                }
        }
        cur ^= 1;
    }

    const int rBase = mBase + warp_m + (lane >> 2);
    const int cBase = nBase + warp_n + (lane & 3) * 2;
    #pragma unroll
    for (int mi = 0; mi < 4; mi++) {
        #pragma unroll
        for (int ni = 0; ni < 4; ni++) {
            #pragma unroll
            for (int half = 0; half < 2; half++) {
                const int m = rBase + mi * 16 + half * 8;
                const int n = cBase + ni * 8;
                out[(size_t)m * DMODEL + n]     = acc[mi][ni][half * 2]     + bias[n];
                out[(size_t)m * DMODEL + n + 1] = acc[mi][ni][half * 2 + 1] + bias[n + 1];
            }
        }
    }
}

// ---------------------------------------------------------------------------
// Tensor-core flash attention (causal), fp16 asymmetric 2-term (unchanged R8
// except ctx epilogue now writes fp16 hi/lo).
// q-tile 128 rows, 256 threads (8 warps), k-tile 64, cp.async double-buffered.
// ---------------------------------------------------------------------------
#define ALDT   72
#define KT_B   9216                        // 64x72 fp16 tile, bytes
#define AST_B  (2 * KT_B)                  // 18432
#define P_OFF  (2 * AST_B)                 // 36864
#define PT_B   (128 * ALDT * 2)            // 18432 (128x72 fp16)
#define ATTN_SMEM (P_OFF + 2 * PT_B)       // 73728

__global__ __launch_bounds__(256)
void attn_mma_kernel()
{
    extern __shared__ __align__(16) char asmem[];
    const uint32_t abase = smem_u32(asmem);

    const int tid  = threadIdx.x;
    const int w    = tid >> 5;
    const int lane = tid & 31;
    const int qi   = gridDim.x - 1 - blockIdx.x;    // long CTAs first
    const int bh   = blockIdx.y;
    const int qBase = qi * 128;
    const int nkt  = 2 * qi + 2;
    const size_t hOff = (size_t)bh * SEQ * HDIM;    // q,k: [bh][s][hd]
    const size_t vOff = (size_t)bh * HDIM * SEQ;    // v^T: [bh][hd][s]

    auto stageKV = [&](uint32_t su, int kBase) {
        #pragma unroll
        for (int it = 0; it < 2; it++) {
            const int slot = tid + it * 256;          // 0..511
            const int row = slot >> 3, c8 = slot & 7;
            const uint32_t so = 2 * (uint32_t)(row * ALDT + c8 * 8);
            cp_async16(su + so,        g_kf + hOff + (size_t)(kBase + row) * HDIM + c8 * 8);
            cp_async16(su + KT_B + so, g_vf + vOff + (size_t)row * SEQ + kBase + c8 * 8);
        }
    };

    stageKV(abase, 0);
    CP_COMMIT();

    // Stage Q (128x64 fp16 hi/lo) through P buffers; pull A-frags to registers
    {
        __half* sPh = reinterpret_cast<__half*>(asmem + P_OFF);
        __half* sPl = reinterpret_cast<__half*>(asmem + P_OFF + PT_B);
        #pragma unroll
        for (int it = 0; it < 4; it++) {
            const int slot = tid + it * 256;          // 0..1023
            const int row = slot >> 3, c8 = slot & 7;
            const size_t g = hOff + (size_t)(qBase + row) * HDIM + c8 * 8;
            *reinterpret_cast<uint4*>(sPh + row * ALDT + c8 * 8) =
                *reinterpret_cast<const uint4*>(g_qh + g);
            *reinterpret_cast<uint4*>(sPl + row * ALDT + c8 * 8) =
                *reinterpret_cast<const uint4*>(g_ql + g);
        }
    }
    __syncthreads();

    uint32_t qh[4][4], ql[4][4];
    {
        const uint32_t qa = abase + P_OFF +
            2 * ((uint32_t)(w * 16 + (lane & 15)) * ALDT + (lane >> 4) * 8);
        #pragma unroll
        for (int t = 0; t < 4; t++) {
            ldmatrix_x4(qh[t], qa + 32 * t);
            ldmatrix_x4(ql[t], qa + PT_B + 32 * t);
        }
    }

    float O[8][4];
    #pragma unroll
    for (int j = 0; j < 8; j++)
        #pragma unroll
        for (int e = 0; e < 4; e++) O[j][e] = 0.0f;
    float m0 = -1e30f, m1 = -1e30f, l0 = 0.0f, l1 = 0.0f;

    const int rl0 = w * 16 + (lane >> 2);       // local row (0..127)
    const int c0  = 2 * (lane & 3);
    const uint32_t pa = abase + P_OFF +
        2 * ((uint32_t)(w * 16 + (lane & 15)) * ALDT + (lane >> 4) * 8);

    int cur = 0;
    for (int kt = 0; kt < nkt; kt++) {
        const int kBase = kt * 64;
        CP_WAIT0();
        __syncthreads();
        if (kt + 1 < nkt) {
            stageKV(abase + (uint32_t)((cur ^ 1) * AST_B), (kt + 1) * 64);
            CP_COMMIT();
        }
        const uint32_t uK = abase + (uint32_t)(cur * AST_B);
        const uint32_t uV = uK + KT_B;
        cur ^= 1;

        const int d = kBase - qBase;
        if (d > w * 16 + 15) continue;          // warp fully masked

        // --- S = (Qh + Ql) K ---
        float s[8][4];
        #pragma unroll
        for (int j = 0; j < 8; j++)
            #pragma unroll
            for (int e = 0; e < 4; e++) s[j][e] = 0.0f;

        #pragma unroll
        for (int t = 0; t < 4; t++) {
            #pragma unroll
            for (int jj = 0; jj < 4; jj++) {
                const uint32_t ba = uK + 2 * ((uint32_t)(16 * jj + 8 * (lane >> 4) + (lane & 7)) * ALDT
                                              + 16 * t + 8 * ((lane >> 3) & 1));
                uint32_t kf4[4];
                ldmatrix_x4(kf4, ba);
                mma_f16(s[2 * jj],     qh[t], kf4);
                mma_f16(s[2 * jj],     ql[t], kf4);
                mma_f16(s[2 * jj + 1], qh[t], kf4 + 2);
                mma_f16(s[2 * jj + 1], ql[t], kf4 + 2);
            }
        }

        // --- Causal mask (last two tiles only) ---
        if (kt >= nkt - 2) {
            #pragma unroll
            for (int j = 0; j < 8; j++) {
                #pragma unroll
                for (int e = 0; e < 2; e++) {
                    const int col = 8 * j + c0 + e + d;
                    if (col > rl0)     s[j][e]     = -1e30f;
                    if (col > rl0 + 8) s[j][2 + e] = -1e30f;
                }
            }
        }

        // --- Online softmax ---
        float mt0 = -1e30f, mt1 = -1e30f;
        #pragma unroll
        for (int j = 0; j < 8; j++) {
            mt0 = fmaxf(mt0, fmaxf(s[j][0], s[j][1]));
            mt1 = fmaxf(mt1, fmaxf(s[j][2], s[j][3]));
        }
        mt0 = fmaxf(mt0, __shfl_xor_sync(0xffffffffu, mt0, 1));
        mt0 = fmaxf(mt0, __shfl_xor_sync(0xffffffffu, mt0, 2));
        mt1 = fmaxf(mt1, __shfl_xor_sync(0xffffffffu, mt1, 1));
        mt1 = fmaxf(mt1, __shfl_xor_sync(0xffffffffu, mt1, 2));

        const float mn0 = fmaxf(m0, mt0);
        const float mn1 = fmaxf(m1, mt1);
        const float cr0 = __expf(m0 - mn0);
        const float cr1 = __expf(m1 - mn1);
        m0 = mn0; m1 = mn1;

        float ls0 = 0.0f, ls1 = 0.0f;
        #pragma unroll
        for (int j = 0; j < 8; j++) {
            s[j][0] = __expf(s[j][0] - mn0);
            s[j][1] = __expf(s[j][1] - mn0);
            s[j][2] = __expf(s[j][2] - mn1);
            s[j][3] = __expf(s[j][3] - mn1);
            ls0 += s[j][0] + s[j][1];
            ls1 += s[j][2] + s[j][3];
        }
        ls0 += __shfl_xor_sync(0xffffffffu, ls0, 1);
        ls0 += __shfl_xor_sync(0xffffffffu, ls0, 2);
        ls1 += __shfl_xor_sync(0xffffffffu, ls1, 1);
        ls1 += __shfl_xor_sync(0xffffffffu, ls1, 2);
        l0 = l0 * cr0 + ls0;
        l1 = l1 * cr1 + ls1;
        #pragma unroll
        for (int j = 0; j < 8; j++) {
            O[j][0] *= cr0; O[j][1] *= cr0;
            O[j][2] *= cr1; O[j][3] *= cr1;
        }

        // --- Store P (fp16 hi/lo): same-warp rows only ---
        __half* sPh = reinterpret_cast<__half*>(asmem + P_OFF);
        __half* sPl = reinterpret_cast<__half*>(asmem + P_OFF + PT_B);
        #pragma unroll
        for (int j = 0; j < 8; j++) {
            const int col = 8 * j + c0;
            __half h0, l0h, h1, l1h;
            split2h(s[j][0], h0, l0h);
            split2h(s[j][1], h1, l1h);
            *reinterpret_cast<__half2*>(sPh + rl0 * ALDT + col) = __halves2half2(h0, h1);
            *reinterpret_cast<__half2*>(sPl + rl0 * ALDT + col) = __halves2half2(l0h, l1h);
            split2h(s[j][2], h0, l0h);
            split2h(s[j][3], h1, l1h);
            *reinterpret_cast<__half2*>(sPh + (rl0 + 8) * ALDT + col) = __halves2half2(h0, h1);
            *reinterpret_cast<__half2*>(sPl + (rl0 + 8) * ALDT + col) = __halves2half2(l0h, l1h);
        }
        __syncwarp();

        // --- O += (Ph + Pl) V ---
        #pragma unroll
        for (int t = 0; t < 4; t++) {
            uint32_t ph4[4], pl4[4];
            ldmatrix_x4(ph4, pa + 32 * t);
            ldmatrix_x4(pl4, pa + PT_B + 32 * t);
            #pragma unroll
            for (int jj = 0; jj < 4; jj++) {
                const uint32_t va = uV + 2 * ((uint32_t)(16 * jj + 8 * (lane >> 4) + (lane & 7)) * ALDT
                                              + 16 * t + 8 * ((lane >> 3) & 1));
                uint32_t vf4[4];
                ldmatrix_x4(vf4, va);
                mma_f16(O[2 * jj],     ph4, vf4);
                mma_f16(O[2 * jj],     pl4, vf4);
                mma_f16(O[2 * jj + 1], ph4, vf4 + 2);
                mma_f16(O[2 * jj + 1], pl4, vf4 + 2);
            }
        }
    }

    // --- Epilogue: ctx fp16 hi/lo to [b*SEQ+s][DMODEL] ---
    const float inv0 = 1.0f / l0;
    const float inv1 = 1.0f / l1;
    const int b    = bh >> 4;
    const int head = bh & 15;
    const int r0   = qBase + rl0;
    #pragma unroll
    for (int j = 0; j < 8; j++) {
        const int col = head * HDIM + 8 * j + c0;
        const size_t i0 = (size_t)(b * SEQ + r0) * DMODEL + col;
        const size_t i1 = (size_t)(b * SEQ + r0 + 8) * DMODEL + col;
        __half h0, l0h, h1, l1h;
        split2h(O[j][0] * inv0, h0, l0h);
        split2h(O[j][1] * inv0, h1, l1h);
        *reinterpret_cast<__half2*>(g_ch + i0) = __halves2half2(h0, h1);
        *reinterpret_cast<__half2*>(g_cl + i0) = __halves2half2(l0h, l1h);
        split2h(O[j][2] * inv1, h0, l0h);
        split2h(O[j][3] * inv1, h1, l1h);
        *reinterpret_cast<__half2*>(g_ch + i1) = __halves2half2(h0, h1);
        *reinterpret_cast<__half2*>(g_cl + i1) = __halves2half2(l0h, l1h);
    }
}

// ---------------------------------------------------------------------------
// Launch
// ---------------------------------------------------------------------------
extern "C" void kernel_launch(void* const* d_in, const int* in_sizes, int n_in,
                              void* d_out, int out_size)
{
    const float* x  = (const float*)d_in[0];
    const float* wq = (const float*)d_in[1];
    const float* bq = (const float*)d_in[2];
    const float* wk = (const float*)d_in[3];
    const float* bk = (const float*)d_in[4];
    const float* wv = (const float*)d_in[5];
    const float* bv = (const float*)d_in[6];
    const float* wo = (const float*)d_in[7];
    const float* bo = (const float*)d_in[8];
    float* out = (float*)d_out;

    __half *xh, *xl, *wf, *qh, *ql, *kf, *vf, *ch, *cl;
    cudaGetSymbolAddress((void**)&xh, g_xh);
    cudaGetSymbolAddress((void**)&xl, g_xl);
    cudaGetSymbolAddress((void**)&wf, g_wf);
    cudaGetSymbolAddress((void**)&qh, g_qh);
    cudaGetSymbolAddress((void**)&ql, g_ql);
    cudaGetSymbolAddress((void**)&kf, g_kf);
    cudaGetSymbolAddress((void**)&vf, g_vf);
    cudaGetSymbolAddress((void**)&ch, g_ch);
    cudaGetSymbolAddress((void**)&cl, g_cl);

    const int NX = MROWS * DMODEL;
    const int NW = DMODEL * DMODEL;
    const float* wsrc[4] = {wq, wk, wv, wo};

    split_f16_kernel<<<NX / 4 / 256, 256>>>(x, xh, xl, NX);
    for (int i = 0; i < 4; i++)
        cvt_f16_kernel<<<NW / 4 / 256, 256>>>(wsrc[i], wf + (size_t)i * NW, NW);

    cudaFuncSetAttribute(mma_gemm_qkv, cudaFuncAttributeMaxDynamicSharedMemorySize, GEMM_SMEM);
    cudaFuncSetAttribute(mma_gemm_out, cudaFuncAttributeMaxDynamicSharedMemorySize, GEMM_SMEM);
    cudaFuncSetAttribute(attn_mma_kernel, cudaFuncAttributeMaxDynamicSharedMemorySize, ATTN_SMEM);

    // Merged Q/K/V projections: grid (24, 32)
    dim3 qkvGrid(24, MROWS / 128);
    mma_gemm_qkv<<<qkvGrid, 256, GEMM_SMEM>>>(xh, xl, wf, bq, bk, bv, qh, ql, kf, vf);

    // Tensor-core flash attention: 128-row q tiles
    dim3 attnGrid(SEQ / 128, BATCH * NHEAD);
    attn_mma_kernel<<<attnGrid, 256, ATTN_SMEM>>>();

    // Output projection (fp32 out)
    dim3 gemmGrid(DMODEL / 128, MROWS / 128);
    mma_gemm_out<<<gemmGrid, 256, GEMM_SMEM>>>(ch, cl, wf + 3 * (size_t)NW, bo, out);
}

// round 10
// speedup vs baseline: 1.9012x; 1.2985x over previous
#include <cuda_runtime.h>
#include <cuda_fp16.h>
#include <cstdint>

#define BATCH  2
#define SEQ    2048
#define DMODEL 1024
#define NHEAD  16
#define HDIM   64
#define MROWS  (BATCH * SEQ)       // 4096

// ---------------------------------------------------------------------------
// Scratch (allocation-free rule: __device__ globals)
// ---------------------------------------------------------------------------
__device__ __half g_xh[MROWS * DMODEL];       // x split fp16 hi/lo
__device__ __half g_xl[MROWS * DMODEL];
__device__ __half g_wf[4][DMODEL * DMODEL];   // wq,wk,wv,wo single fp16
__device__ __half g_qf[MROWS * DMODEL];       // q single fp16 [bh][s][hd], scaled 0.125
__device__ __half g_kf[MROWS * DMODEL];       // k single fp16 [bh][s][hd]
__device__ __half g_vf[MROWS * DMODEL];       // v single fp16 TRANSPOSED [bh][hd][s]
__device__ __half g_cf[MROWS * DMODEL];       // ctx single fp16 [b*s][d]

// ---------------------------------------------------------------------------
// Warp-MMA + cp.async helpers (base compute_103 PTX)
// ---------------------------------------------------------------------------
__device__ __forceinline__ uint32_t smem_u32(const void* p) {
    uint32_t a;
    asm("{ .reg .u64 t; cvta.to.shared.u64 t, %1; cvt.u32.u64 %0, t; }"
        : "=r"(a) : "l"(p));
    return a;
}

__device__ __forceinline__ void ldmatrix_x4(uint32_t* r, uint32_t addr) {
    asm volatile("ldmatrix.sync.aligned.m8n8.x4.shared.b16 {%0,%1,%2,%3}, [%4];"
                 : "=r"(r[0]), "=r"(r[1]), "=r"(r[2]), "=r"(r[3]) : "r"(addr));
}

__device__ __forceinline__ void mma_f16(float* c, const uint32_t* a, const uint32_t* b) {
    asm volatile(
        "mma.sync.aligned.m16n8k16.row.col.f32.f16.f16.f32 "
        "{%0,%1,%2,%3}, {%4,%5,%6,%7}, {%8,%9}, {%0,%1,%2,%3};"
        : "+f"(c[0]), "+f"(c[1]), "+f"(c[2]), "+f"(c[3])
        : "r"(a[0]), "r"(a[1]), "r"(a[2]), "r"(a[3]), "r"(b[0]), "r"(b[1]));
}

__device__ __forceinline__ void cp_async16(uint32_t dst, const void* src) {
    asm volatile("cp.async.cg.shared.global [%0], [%1], 16;" :: "r"(dst), "l"(src));
}
#define CP_COMMIT() asm volatile("cp.async.commit_group;" ::: "memory")
#define CP_WAIT0()  asm volatile("cp.async.wait_group 0;" ::: "memory")

__device__ __forceinline__ void split2h(float v, __half& h, __half& l) {
    h = __float2half(v);
    l = __float2half(v - __half2float(h));
}

// ---------------------------------------------------------------------------
// Merged prep: blocks [0,4096) split x to fp16 hi/lo; blocks [4096,8192)
// convert the 4 weight matrices to single fp16.
// ---------------------------------------------------------------------------
__global__ __launch_bounds__(256)
void prep_kernel(const float* __restrict__ x,
                 const float* __restrict__ wq, const float* __restrict__ wk,
                 const float* __restrict__ wv, const float* __restrict__ wo,
                 __half* __restrict__ xh, __half* __restrict__ xl,
                 __half* __restrict__ wf)
{
    const int bid = blockIdx.x;
    if (bid < 4096) {
        const int i4 = (bid * 256 + threadIdx.x) * 4;
        float4 f = *reinterpret_cast<const float4*>(x + i4);
        __half h0, h1, l0, l1;
        split2h(f.x, h0, l0); split2h(f.y, h1, l1);
        *reinterpret_cast<__half2*>(xh + i4) = __halves2half2(h0, h1);
        *reinterpret_cast<__half2*>(xl + i4) = __halves2half2(l0, l1);
        split2h(f.z, h0, l0); split2h(f.w, h1, l1);
        *reinterpret_cast<__half2*>(xh + i4 + 2) = __halves2half2(h0, h1);
        *reinterpret_cast<__half2*>(xl + i4 + 2) = __halves2half2(l0, l1);
    } else {
        const int idx = bid - 4096;
        const int wi  = idx >> 10;            // 1024 blocks per weight
        const int i4  = ((idx & 1023) * 256 + threadIdx.x) * 4;
        const float* src = (wi == 0) ? wq : (wi == 1) ? wk : (wi == 2) ? wv : wo;
        __half* dst = wf + (size_t)wi * DMODEL * DMODEL;
        float4 f = *reinterpret_cast<const float4*>(src + i4);
        *reinterpret_cast<__half2*>(dst + i4)     = __halves2half2(__float2half(f.x), __float2half(f.y));
        *reinterpret_cast<__half2*>(dst + i4 + 2) = __halves2half2(__float2half(f.z), __float2half(f.w));
    }
}

// ---------------------------------------------------------------------------
// GEMM tiling constants
// CTA 128x128 tile, 8 warps (2x4), warp tile 64x32, K-chunk 64, 2 stages.
// ---------------------------------------------------------------------------
#define LDT       72
#define TILE_ELEM (128 * LDT)
#define TILE_B    (TILE_ELEM * 2)          // 18432 bytes
#define STAGE3_B  (3 * TILE_B)             // QKV stage: Ah, Al, W
#define QKV_SMEM  (2 * STAGE3_B)           // 110592
#define STAGE2_B  (2 * TILE_B)             // out stage: A, W
#define OUT_SMEM  (2 * STAGE2_B)           // 73728

// ---------------------------------------------------------------------------
// Merged QKV GEMM: grid (24, 32); which = blockIdx.x>>3 selects wq/wk/wv.
// 2-term A (x hi/lo), single-fp16 W. Outputs single fp16.
// which 0 -> q [bh][s][hd] scaled 0.125; 1 -> k [bh][s][hd]; 2 -> v^T [bh][hd][s]
// ---------------------------------------------------------------------------
__global__ __launch_bounds__(256)
void mma_gemm_qkv(const __half* __restrict__ xh,
                  const __half* __restrict__ xl,
                  const __half* __restrict__ wf,
                  const float* __restrict__ bq,
                  const float* __restrict__ bk,
                  const float* __restrict__ bv,
                  __half* __restrict__ qf,
                  __half* __restrict__ kf,
                  __half* __restrict__ vf)
{
    extern __shared__ __align__(16) char smem[];
    const uint32_t sbase = smem_u32(smem);

    const int tid  = threadIdx.x;
    const int wid  = tid >> 5;
    const int lane = tid & 31;
    const int which = blockIdx.x >> 3;
    const int nBase = (blockIdx.x & 7) * 128;
    const int mBase = blockIdx.y * 128;
    const int warp_m = (wid >> 2) * 64;
    const int warp_n = (wid & 3) * 32;

    const size_t NW = (size_t)DMODEL * DMODEL;
    const __half* W = wf + which * NW;
    const float* bias = (which == 0) ? bq : (which == 1) ? bk : bv;
    const float scale = (which == 0) ? 0.125f : 1.0f;
    const __half* srcs[3] = {xh, xl, W};

    auto stage = [&](uint32_t sdst, int kc) {
        #pragma unroll
        for (int t = 0; t < 3; t++) {
            const __half* src = srcs[t];
            const int rb = (t < 2) ? mBase : nBase;
            #pragma unroll
            for (int it = 0; it < 4; it++) {
                const int slot = tid + it * 256;
                const int row  = slot >> 3;
                const int c8   = slot & 7;
                cp_async16(sdst + t * TILE_B + 2 * (uint32_t)(row * LDT + c8 * 8),
                           src + (size_t)(rb + row) * DMODEL + kc + c8 * 8);
            }
        }
    };

    float acc[4][4][4];
    #pragma unroll
    for (int mi = 0; mi < 4; mi++)
        #pragma unroll
        for (int ni = 0; ni < 4; ni++)
            #pragma unroll
            for (int e = 0; e < 4; e++) acc[mi][ni][e] = 0.0f;

    const uint32_t aRow = (uint32_t)(warp_m + (lane & 15)) * LDT + (lane >> 4) * 8;
    const uint32_t bRow = (uint32_t)(warp_n + 8 * (lane >> 4) + (lane & 7)) * LDT
                          + 8 * ((lane >> 3) & 1);

    stage(sbase, 0);
    CP_COMMIT();

    int cur = 0;
    for (int kc = 0; kc < DMODEL; kc += 64) {
        CP_WAIT0();
        __syncthreads();
        if (kc + 64 < DMODEL) {
            stage(sbase + (uint32_t)((cur ^ 1) * STAGE3_B), kc + 64);
            CP_COMMIT();
        }

        const uint32_t uA = sbase + (uint32_t)(cur * STAGE3_B) + 2 * aRow;
        const uint32_t uB = sbase + (uint32_t)(cur * STAGE3_B + 2 * TILE_B) + 2 * bRow;

        #pragma unroll
        for (int ks = 0; ks < 4; ks++) {
            const uint32_t kOff = 2 * (uint32_t)(ks * 16);
            uint32_t ah[4][4], al[4][4], w4[2][4];
            #pragma unroll
            for (int mi = 0; mi < 4; mi++) {
                const uint32_t addr = uA + kOff + 2 * (uint32_t)(mi * 16) * LDT;
                ldmatrix_x4(ah[mi], addr);
                ldmatrix_x4(al[mi], addr + TILE_B);
            }
            #pragma unroll
            for (int np = 0; np < 2; np++) {
                const uint32_t addr = uB + kOff + 2 * (uint32_t)(np * 16) * LDT;
                ldmatrix_x4(w4[np], addr);
            }
            #pragma unroll
            for (int mi = 0; mi < 4; mi++)
                #pragma unroll
                for (int ni = 0; ni < 4; ni++) {
                    const uint32_t* b = &w4[ni >> 1][2 * (ni & 1)];
                    mma_f16(acc[mi][ni], ah[mi], b);
                    mma_f16(acc[mi][ni], al[mi], b);
                }
        }
        cur ^= 1;
    }

    const int rBase = mBase + warp_m + (lane >> 2);
    const int cBase = nBase + warp_n + (lane & 3) * 2;
    #pragma unroll
    for (int mi = 0; mi < 4; mi++) {
        #pragma unroll
        for (int ni = 0; ni < 4; ni++) {
            #pragma unroll
            for (int half = 0; half < 2; half++) {
                const int m = rBase + mi * 16 + half * 8;
                const int n = cBase + ni * 8;
                const float v0 = (acc[mi][ni][half * 2]     + bias[n])     * scale;
                const float v1 = (acc[mi][ni][half * 2 + 1] + bias[n + 1]) * scale;
                const int b  = m >> 11;
                const int s  = m & 2047;
                const int h  = n >> 6;
                const int hd = n & 63;
                if (which < 2) {
                    const size_t idx = (((size_t)(b * NHEAD + h) * SEQ) + s) * HDIM + hd;
                    __half* dst = (which == 0) ? qf : kf;
                    *reinterpret_cast<__half2*>(dst + idx) =
                        __halves2half2(__float2half(v0), __float2half(v1));
                } else {
                    const size_t idx = (((size_t)(b * NHEAD + h) * HDIM) + hd) * SEQ + s;
                    vf[idx]       = __float2half(v0);
                    vf[idx + SEQ] = __float2half(v1);
                }
            }
        }
    }
}

// ---------------------------------------------------------------------------
// Output-projection GEMM (fp32 out), plain fp16 (single-term A and W).
// ---------------------------------------------------------------------------
__global__ __launch_bounds__(256)
void mma_gemm_out(const __half* __restrict__ A,
                  const __half* __restrict__ W,
                  const float* __restrict__ bias,
                  float* __restrict__ out)
{
    extern __shared__ __align__(16) char smem[];
    const uint32_t sbase = smem_u32(smem);

    const int tid  = threadIdx.x;
    const int wid  = tid >> 5;
    const int lane = tid & 31;
    const int mBase = blockIdx.y * 128;
    const int nBase = blockIdx.x * 128;
    const int warp_m = (wid >> 2) * 64;
    const int warp_n = (wid & 3) * 32;

    const __half* srcs[2] = {A, W};

    auto stage = [&](uint32_t sdst, int kc) {
        #pragma unroll
        for (int t = 0; t < 2; t++) {
            const __half* src = srcs[t];
            const int rb = (t == 0) ? mBase : nBase;
            #pragma unroll
            for (int it = 0; it < 4; it++) {
                const int slot = tid + it * 256;
                const int row  = slot >> 3;
                const int c8   = slot & 7;
                cp_async16(sdst + t * TILE_B + 2 * (uint32_t)(row * LDT + c8 * 8),
                           src + (size_t)(rb + row) * DMODEL + kc + c8 * 8);
            }
        }
    };

    float acc[4][4][4];
    #pragma unroll
    for (int mi = 0; mi < 4; mi++)
        #pragma unroll
        for (int ni = 0; ni < 4; ni++)
            #pragma unroll
            for (int e = 0; e < 4; e++) acc[mi][ni][e] = 0.0f;

    const uint32_t aRow = (uint32_t)(warp_m + (lane & 15)) * LDT + (lane >> 4) * 8;
    const uint32_t bRow = (uint32_t)(warp_n + 8 * (lane >> 4) + (lane & 7)) * LDT
                          + 8 * ((lane >> 3) & 1);

    stage(sbase, 0);
    CP_COMMIT();

    int cur = 0;
    for (int kc = 0; kc < DMODEL; kc += 64) {
        CP_WAIT0();
        __syncthreads();
        if (kc + 64 < DMODEL) {
            stage(sbase + (uint32_t)((cur ^ 1) * STAGE2_B), kc + 64);
            CP_COMMIT();
        }

        const uint32_t uA = sbase + (uint32_t)(cur * STAGE2_B) + 2 * aRow;
        const uint32_t uB = sbase + (uint32_t)(cur * STAGE2_B + TILE_B) + 2 * bRow;

        #pragma unroll
        for (int ks = 0; ks < 4; ks++) {
            const uint32_t kOff = 2 * (uint32_t)(ks * 16);
            uint32_t a4[4][4], w4[2][4];
            #pragma unroll
            for (int mi = 0; mi < 4; mi++)
                ldmatrix_x4(a4[mi], uA + kOff + 2 * (uint32_t)(mi * 16) * LDT);
            #pragma unroll
            for (int np = 0; np < 2; np++)
                ldmatrix_x4(w4[np], uB + kOff + 2 * (uint32_t)(np * 16) * LDT);
            #pragma unroll
            for (int mi = 0; mi < 4; mi++)
                #pragma unroll
                for (int ni = 0; ni < 4; ni++)
                    mma_f16(acc[mi][ni], a4[mi], &w4[ni >> 1][2 * (ni & 1)]);
        }
        cur ^= 1;
    }

    const int rBase = mBase + warp_m + (lane >> 2);
    const int cBase = nBase + warp_n + (lane & 3) * 2;
    #pragma unroll
    for (int mi = 0; mi < 4; mi++) {
        #pragma unroll
        for (int ni = 0; ni < 4; ni++) {
            #pragma unroll
            for (int half = 0; half < 2; half++) {
                const int m = rBase + mi * 16 + half * 8;
                const int n = cBase + ni * 8;
                out[(size_t)m * DMODEL + n]     = acc[mi][ni][half * 2]     + bias[n];
                out[(size_t)m * DMODEL + n + 1] = acc[mi][ni][half * 2 + 1] + bias[n + 1];
            }
        }
    }
}

// ---------------------------------------------------------------------------
// Tensor-core flash attention (causal), all-single fp16 operands, fp32 softmax.
// q-tile 128 rows, 256 threads (8 warps), k-tile 64, cp.async double-buffered.
// Smem: stage s at s*18432 {Kf, Vf each 64x72}; P/Q (128x72) at 36864.
// ---------------------------------------------------------------------------
#define ALDT   72
#define KT_B   9216                        // 64x72 fp16 tile, bytes
#define AST_B  (2 * KT_B)                  // 18432
#define P_OFF  (2 * AST_B)                 // 36864
#define PT_B   (128 * ALDT * 2)            // 18432 (128x72 fp16)
#define ATTN_SMEM (P_OFF + PT_B)           // 55296

__global__ __launch_bounds__(256)
void attn_mma_kernel()
{
    extern __shared__ __align__(16) char asmem[];
    const uint32_t abase = smem_u32(asmem);

    const int tid  = threadIdx.x;
    const int w    = tid >> 5;
    const int lane = tid & 31;
    const int qi   = gridDim.x - 1 - blockIdx.x;    // long CTAs first
    const int bh   = blockIdx.y;
    const int qBase = qi * 128;
    const int nkt  = 2 * qi + 2;
    const size_t hOff = (size_t)bh * SEQ * HDIM;    // q,k: [bh][s][hd]
    const size_t vOff = (size_t)bh * HDIM * SEQ;    // v^T: [bh][hd][s]

    auto stageKV = [&](uint32_t su, int kBase) {
        #pragma unroll
        for (int it = 0; it < 2; it++) {
            const int slot = tid + it * 256;          // 0..511
            const int row = slot >> 3, c8 = slot & 7;
            const uint32_t so = 2 * (uint32_t)(row * ALDT + c8 * 8);
            cp_async16(su + so,        g_kf + hOff + (size_t)(kBase + row) * HDIM + c8 * 8);
            cp_async16(su + KT_B + so, g_vf + vOff + (size_t)row * SEQ + kBase + c8 * 8);
        }
    };

    stageKV(abase, 0);
    CP_COMMIT();

    // Stage Q (128x64 fp16) through the P buffer; pull A-frags to registers
    {
        __half* sP = reinterpret_cast<__half*>(asmem + P_OFF);
        #pragma unroll
        for (int it = 0; it < 4; it++) {
            const int slot = tid + it * 256;          // 0..1023
            const int row = slot >> 3, c8 = slot & 7;
            *reinterpret_cast<uint4*>(sP + row * ALDT + c8 * 8) =
                *reinterpret_cast<const uint4*>(g_qf + hOff + (size_t)(qBase + row) * HDIM + c8 * 8);
        }
    }
    __syncthreads();

    uint32_t qh[4][4];
    {
        const uint32_t qa = abase + P_OFF +
            2 * ((uint32_t)(w * 16 + (lane & 15)) * ALDT + (lane >> 4) * 8);
        #pragma unroll
        for (int t = 0; t < 4; t++)
            ldmatrix_x4(qh[t], qa + 32 * t);
    }

    float O[8][4];
    #pragma unroll
    for (int j = 0; j < 8; j++)
        #pragma unroll
        for (int e = 0; e < 4; e++) O[j][e] = 0.0f;
    float m0 = -1e30f, m1 = -1e30f, l0 = 0.0f, l1 = 0.0f;

    const int rl0 = w * 16 + (lane >> 2);       // local row (0..127)
    const int c0  = 2 * (lane & 3);
    const uint32_t pa = abase + P_OFF +
        2 * ((uint32_t)(w * 16 + (lane & 15)) * ALDT + (lane >> 4) * 8);

    int cur = 0;
    for (int kt = 0; kt < nkt; kt++) {
        const int kBase = kt * 64;
        CP_WAIT0();
        __syncthreads();
        if (kt + 1 < nkt) {
            stageKV(abase + (uint32_t)((cur ^ 1) * AST_B), (kt + 1) * 64);
            CP_COMMIT();
        }
        const uint32_t uK = abase + (uint32_t)(cur * AST_B);
        const uint32_t uV = uK + KT_B;
        cur ^= 1;

        const int d = kBase - qBase;
        if (d > w * 16 + 15) continue;          // warp fully masked

        // --- S = Q K (single fp16 both sides) ---
        float s[8][4];
        #pragma unroll
        for (int j = 0; j < 8; j++)
            #pragma unroll
            for (int e = 0; e < 4; e++) s[j][e] = 0.0f;

        #pragma unroll
        for (int t = 0; t < 4; t++) {
            #pragma unroll
            for (int jj = 0; jj < 4; jj++) {
                const uint32_t ba = uK + 2 * ((uint32_t)(16 * jj + 8 * (lane >> 4) + (lane & 7)) * ALDT
                                              + 16 * t + 8 * ((lane >> 3) & 1));
                uint32_t kf4[4];
                ldmatrix_x4(kf4, ba);
                mma_f16(s[2 * jj],     qh[t], kf4);
                mma_f16(s[2 * jj + 1], qh[t], kf4 + 2);
            }
        }

        // --- Causal mask (last two tiles only) ---
        if (kt >= nkt - 2) {
            #pragma unroll
            for (int j = 0; j < 8; j++) {
                #pragma unroll
                for (int e = 0; e < 2; e++) {
                    const int col = 8 * j + c0 + e + d;
                    if (col > rl0)     s[j][e]     = -1e30f;
                    if (col > rl0 + 8) s[j][2 + e] = -1e30f;
                }
            }
        }

        // --- Online softmax ---
        float mt0 = -1e30f, mt1 = -1e30f;
        #pragma unroll
        for (int j = 0; j < 8; j++) {
            mt0 = fmaxf(mt0, fmaxf(s[j][0], s[j][1]));
            mt1 = fmaxf(mt1, fmaxf(s[j][2], s[j][3]));
        }
        mt0 = fmaxf(mt0, __shfl_xor_sync(0xffffffffu, mt0, 1));
        mt0 = fmaxf(mt0, __shfl_xor_sync(0xffffffffu, mt0, 2));
        mt1 = fmaxf(mt1, __shfl_xor_sync(0xffffffffu, mt1, 1));
        mt1 = fmaxf(mt1, __shfl_xor_sync(0xffffffffu, mt1, 2));

        const float mn0 = fmaxf(m0, mt0);
        const float mn1 = fmaxf(m1, mt1);
        const float cr0 = __expf(m0 - mn0);
        const float cr1 = __expf(m1 - mn1);
        m0 = mn0; m1 = mn1;

        float ls0 = 0.0f, ls1 = 0.0f;
        #pragma unroll
        for (int j = 0; j < 8; j++) {
            s[j][0] = __expf(s[j][0] - mn0);
            s[j][1] = __expf(s[j][1] - mn0);
            s[j][2] = __expf(s[j][2] - mn1);
            s[j][3] = __expf(s[j][3] - mn1);
            ls0 += s[j][0] + s[j][1];
            ls1 += s[j][2] + s[j][3];
        }
        ls0 += __shfl_xor_sync(0xffffffffu, ls0, 1);
        ls0 += __shfl_xor_sync(0xffffffffu, ls0, 2);
        ls1 += __shfl_xor_sync(0xffffffffu, ls1, 1);
        ls1 += __shfl_xor_sync(0xffffffffu, ls1, 2);
        l0 = l0 * cr0 + ls0;
        l1 = l1 * cr1 + ls1;
        #pragma unroll
        for (int j = 0; j < 8; j++) {
            O[j][0] *= cr0; O[j][1] *= cr0;
            O[j][2] *= cr1; O[j][3] *= cr1;
        }

        // --- Store P (single fp16): same-warp rows only ---
        __half* sP = reinterpret_cast<__half*>(asmem + P_OFF);
        #pragma unroll
        for (int j = 0; j < 8; j++) {
            const int col = 8 * j + c0;
            *reinterpret_cast<__half2*>(sP + rl0 * ALDT + col) =
                __halves2half2(__float2half(s[j][0]), __float2half(s[j][1]));
            *reinterpret_cast<__half2*>(sP + (rl0 + 8) * ALDT + col) =
                __halves2half2(__float2half(s[j][2]), __float2half(s[j][3]));
        }
        __syncwarp();

        // --- O += P V (single fp16 both sides) ---
        #pragma unroll
        for (int t = 0; t < 4; t++) {
            uint32_t ph4[4];
            ldmatrix_x4(ph4, pa + 32 * t);
            #pragma unroll
            for (int jj = 0; jj < 4; jj++) {
                const uint32_t va = uV + 2 * ((uint32_t)(16 * jj + 8 * (lane >> 4) + (lane & 7)) * ALDT
                                              + 16 * t + 8 * ((lane >> 3) & 1));
                uint32_t vf4[4];
                ldmatrix_x4(vf4, va);
                mma_f16(O[2 * jj],     ph4, vf4);
                mma_f16(O[2 * jj + 1], ph4, vf4 + 2);
            }
        }
    }

    // --- Epilogue: ctx single fp16 to [b*SEQ+s][DMODEL] ---
    const float inv0 = 1.0f / l0;
    const float inv1 = 1.0f / l1;
    const int b    = bh >> 4;
    const int head = bh & 15;
    const int r0   = qBase + rl0;
    #pragma unroll
    for (int j = 0; j < 8; j++) {
        const int col = head * HDIM + 8 * j + c0;
        const size_t i0 = (size_t)(b * SEQ + r0) * DMODEL + col;
        const size_t i1 = (size_t)(b * SEQ + r0 + 8) * DMODEL + col;
        *reinterpret_cast<__half2*>(g_cf + i0) =
            __halves2half2(__float2half(O[j][0] * inv0), __float2half(O[j][1] * inv0));
        *reinterpret_cast<__half2*>(g_cf + i1) =
            __halves2half2(__float2half(O[j][2] * inv1), __float2half(O[j][3] * inv1));
    }
}

// ---------------------------------------------------------------------------
// Launch
// ---------------------------------------------------------------------------
extern "C" void kernel_launch(void* const* d_in, const int* in_sizes, int n_in,
                              void* d_out, int out_size)
{
    const float* x  = (const float*)d_in[0];
    const float* wq = (const float*)d_in[1];
    const float* bq = (const float*)d_in[2];
    const float* wk = (const float*)d_in[3];
    const float* bk = (const float*)d_in[4];
    const float* wv = (const float*)d_in[5];
    const float* bv = (const float*)d_in[6];
    const float* wo = (const float*)d_in[7];
    const float* bo = (const float*)d_in[8];
    float* out = (float*)d_out;

    __half *xh, *xl, *wf, *qf, *kf, *vf, *cf;
    cudaGetSymbolAddress((void**)&xh, g_xh);
    cudaGetSymbolAddress((void**)&xl, g_xl);
    cudaGetSymbolAddress((void**)&wf, g_wf);
    cudaGetSymbolAddress((void**)&qf, g_qf);
    cudaGetSymbolAddress((void**)&kf, g_kf);
    cudaGetSymbolAddress((void**)&vf, g_vf);
    cudaGetSymbolAddress((void**)&cf, g_cf);

    const size_t NW = (size_t)DMODEL * DMODEL;

    // Merged prep: x split + 4 weight converts (8192 blocks)
    prep_kernel<<<8192, 256>>>(x, wq, wk, wv, wo, xh, xl, wf);

    cudaFuncSetAttribute(mma_gemm_qkv, cudaFuncAttributeMaxDynamicSharedMemorySize, QKV_SMEM);
    cudaFuncSetAttribute(mma_gemm_out, cudaFuncAttributeMaxDynamicSharedMemorySize, OUT_SMEM);
    cudaFuncSetAttribute(attn_mma_kernel, cudaFuncAttributeMaxDynamicSharedMemorySize, ATTN_SMEM);

    // Merged Q/K/V projections: grid (24, 32)
    dim3 qkvGrid(24, MROWS / 128);
    mma_gemm_qkv<<<qkvGrid, 256, QKV_SMEM>>>(xh, xl, wf, bq, bk, bv, qf, kf, vf);

    // Tensor-core flash attention: 128-row q tiles
    dim3 attnGrid(SEQ / 128, BATCH * NHEAD);
    attn_mma_kernel<<<attnGrid, 256, ATTN_SMEM>>>();

    // Output projection (plain fp16, fp32 out)
    dim3 gemmGrid(DMODEL / 128, MROWS / 128);
    mma_gemm_out<<<gemmGrid, 256, OUT_SMEM>>>(cf, wf + 3 * NW, bo, out);
}